// round 10
// baseline (speedup 1.0000x reference)
#include <cuda_runtime.h>
#include <cuda_bf16.h>

#define BN   4
#define CIN  3
#define CO   64
#define HH   512
#define WW   512
#define SS   (HH*WW)        /* 262144 = 2^18 */
#define NC   (BN*CO)        /* 256 */
#define HR   448
#define MM   (HR*HR)        /* 200704 */
#define NCS  (NC*SS)        /* 67108864 */
#define NCM  (NC*MM)        /* 51380224 */
#define KB   65536          /* bins per channel (16-bit sortable key) */

// ---------------- static device scratch (no runtime allocation) ----------------
__device__ unsigned int g_hist_src_p[NC*KB/2];  // packed u16 counts (32 MB)
__device__ unsigned int g_hist_ref_p[NC*KB/2];  // packed u16 counts (32 MB)
__device__ unsigned int g_cdf_src[NC*KB];       // u32 exclusive CDF (64 MB)
__device__ unsigned int g_cdf_ref[NC*KB];       // u32 exclusive CDF (64 MB)
__device__ unsigned int g_zero[NC];             // oversized zero-bin counts
__device__ float        g_src_sorted[NCS];      // 268 MB sorted src values
__device__ float        g_ref_sorted[NCM];      // 205 MB sorted ref values
__device__ double       g_accum[3];             // content, style, hist sums
__device__ float        g_gram[BN*CO*CO];

// ---------------- helpers ----------------
__device__ __forceinline__ unsigned int f2s(float x) {
    unsigned int u = __float_as_uint(x);
    return (u & 0x80000000u) ? ~u : (u | 0x80000000u);
}
__device__ __forceinline__ float s2f(unsigned int k) {
    unsigned int u = (k & 0x80000000u) ? (k ^ 0x80000000u) : ~k;
    return __uint_as_float(u);
}
__device__ __forceinline__ float key2f(unsigned int k16) {
    return s2f((k16 << 16) | 0x8000u);
}

// packed f32x2 (FFMA2) helpers
__device__ __forceinline__ unsigned long long pk2(float lo, float hi) {
    unsigned long long r;
    asm("mov.b64 %0, {%1, %2};" : "=l"(r) : "f"(lo), "f"(hi));
    return r;
}
__device__ __forceinline__ void upk2(unsigned long long v, float& lo, float& hi) {
    asm("mov.b64 {%0, %1}, %2;" : "=f"(lo), "=f"(hi) : "l"(v));
}
__device__ __forceinline__ unsigned long long fma2(unsigned long long a,
                                                   unsigned long long b,
                                                   unsigned long long c) {
    unsigned long long d;
    asm("fma.rn.f32x2 %0, %1, %2, %3;" : "=l"(d) : "l"(a), "l"(b), "l"(c));
    return d;
}

__device__ __forceinline__ void block_add(double v, double* target) {
    __shared__ double sh[8];
    int tid  = threadIdx.x + threadIdx.y * blockDim.x;
    int lane = tid & 31, wid = tid >> 5;
    int nwarps = (blockDim.x * blockDim.y + 31) >> 5;
    #pragma unroll
    for (int o = 16; o > 0; o >>= 1) v += __shfl_down_sync(0xffffffffu, v, o);
    if (lane == 0) sh[wid] = v;
    __syncthreads();
    if (wid == 0) {
        v = (lane < nwarps) ? sh[lane] : 0.0;
        #pragma unroll
        for (int o = 4; o > 0; o >>= 1) v += __shfl_down_sync(0xffffffffu, v, o);
        if (lane == 0) atomicAdd(target, v);
    }
}

// ---------------- init ----------------
__global__ void init_kernel() {
    int i = blockIdx.x * 256 + threadIdx.x;
    if (i < 3) g_accum[i] = 0.0;
    if (i < BN*CO*CO) g_gram[i] = 0.0f;
}

// ------ conv + bias + relu + content-loss (fused, FFMA2 inner) ------
__global__ void conv_kernel(const float* __restrict__ img, const float* __restrict__ w,
                            const float* __restrict__ b,   const float* __restrict__ ct,
                            float* __restrict__ out) {
    __shared__ float sin[3][10][34];
    __shared__ float sw[27][64];
    __shared__ float sb[64];
    const int n  = blockIdx.z;
    const int x0 = blockIdx.x * 32;
    const int y0 = blockIdx.y * 8;
    const int tid = threadIdx.y * 32 + threadIdx.x;

    for (int i = tid; i < 1728; i += 256) { int co = i / 27, tap = i % 27; sw[tap][co] = w[i]; }
    if (tid < 64) sb[tid] = b[tid];

    const float mean[3] = {0.485f, 0.456f, 0.406f};
    const float istd[3] = {1.f/0.229f, 1.f/0.224f, 1.f/0.225f};
    #pragma unroll
    for (int c = 0; c < 3; c++) {
        for (int i = tid; i < 340; i += 256) {
            int r = i / 34, cc = i % 34;
            int gy = y0 + r - 1, gx = x0 + cc - 1;
            float v = 0.f;
            if (gy >= 0 && gy < HH && gx >= 0 && gx < WW)
                v = (img[((n*3 + c)*HH + gy)*WW + gx] - mean[c]) * istd[c];
            sin[c][r][cc] = v;
        }
    }
    __syncthreads();

    const int px = threadIdx.x, py = threadIdx.y;
    unsigned long long v2[27];
    #pragma unroll
    for (int c = 0; c < 3; c++)
        #pragma unroll
        for (int ky = 0; ky < 3; ky++)
            #pragma unroll
            for (int kx = 0; kx < 3; kx++) {
                float vv = sin[c][py + ky][px + kx];
                v2[c*9 + ky*3 + kx] = pk2(vv, vv);
            }

    const int y = y0 + py, x = x0 + px;
    float fsum = 0.f;
    #pragma unroll
    for (int cb = 0; cb < 64; cb += 16) {
        unsigned long long acc2[8];
        #pragma unroll
        for (int j = 0; j < 8; j++) acc2[j] = *(const unsigned long long*)&sb[cb + 2*j];
        #pragma unroll
        for (int t2 = 0; t2 < 27; t2++) {
            unsigned long long vv = v2[t2];
            #pragma unroll
            for (int j = 0; j < 8; j++)
                acc2[j] = fma2(vv, *(const unsigned long long*)&sw[t2][cb + 2*j], acc2[j]);
        }
        #pragma unroll
        for (int j = 0; j < 8; j++) {
            float f0, f1;
            upk2(acc2[j], f0, f1);
            f0 = f0 > 0.f ? f0 : 0.f;
            f1 = f1 > 0.f ? f1 : 0.f;
            unsigned int ch0 = (unsigned int)(n*64 + cb + 2*j);
            unsigned int oi0 = ch0 * SS + (unsigned int)y * WW + x;
            out[oi0]      = f0;
            out[oi0 + SS] = f1;
            float d0 = f0 - ct[oi0];
            float d1 = f1 - ct[oi0 + SS];
            fsum = fmaf(d0, d0, fsum);
            fsum = fmaf(d1, d1, fsum);
        }
    }
    block_add((double)fsum, &g_accum[0]);
}

// ------ per-channel histogram of feat: warp-aggregated smem atomics ------
// feat values are spatially correlated -> same-bin conflicts within a warp.
// __match_any_sync groups lanes by bin; one atomic per distinct bin per warp.
__global__ void __launch_bounds__(1024) src_hist_kernel(const float4* __restrict__ feat) {
    extern __shared__ unsigned int sh[];  // KB/2 = 32768 words
    __shared__ unsigned int zwarp[32];
    const int ch  = blockIdx.x;
    const int tid = threadIdx.x;
    const int lane = tid & 31, wid = tid >> 5;
    for (int i = tid; i < KB/2; i += 1024) sh[i] = 0;
    __syncthreads();

    const float4* p = feat + (size_t)ch * (SS/4);
    unsigned int zc = 0;
    for (int i = tid; i < SS/4; i += 1024) {
        float4 v = p[i];
        float e[4] = {v.x, v.y, v.z, v.w};
        #pragma unroll
        for (int j = 0; j < 4; j++) {
            float f = e[j];
            if (f == 0.f) { zc++; }
            else {
                unsigned int k = f2s(f) >> 16;
                unsigned int peers = __match_any_sync(__activemask(), k);
                int leader = __ffs(peers) - 1;
                if (lane == leader) {
                    unsigned int cnt = (unsigned int)__popc(peers);
                    atomicAdd(&sh[k >> 1], cnt << ((k & 1) * 16));
                }
            }
        }
    }
    #pragma unroll
    for (int o = 16; o > 0; o >>= 1) zc += __shfl_down_sync(0xffffffffu, zc, o);
    if (lane == 0) zwarp[wid] = zc;
    __syncthreads();
    if (tid == 0) {
        unsigned int s = 0;
        #pragma unroll
        for (int i = 0; i < 32; i++) s += zwarp[i];
        g_zero[ch] = s;
    }

    unsigned int* g = &g_hist_src_p[(size_t)ch * (KB/2)];
    for (int i = tid; i < KB/2; i += 1024) g[i] = sh[i];
}

// ------ per-channel histogram of ref target (random data: plain atomics fine) ------
__global__ void __launch_bounds__(1024) ref_hist_kernel(const float4* __restrict__ vals) {
    extern __shared__ unsigned int sh[];
    const int ch  = blockIdx.x;
    const int tid = threadIdx.x;
    for (int i = tid; i < KB/2; i += 1024) sh[i] = 0;
    __syncthreads();

    const float4* p = vals + (size_t)ch * (MM/4);
    for (int i = tid; i < MM/4; i += 1024) {
        float4 v = p[i];
        float e[4] = {v.x, v.y, v.z, v.w};
        #pragma unroll
        for (int j = 0; j < 4; j++) {
            unsigned int k = f2s(e[j]) >> 16;
            atomicAdd(&sh[k >> 1], 1u << ((k & 1) * 16));
        }
    }
    __syncthreads();

    unsigned int* g = &g_hist_ref_p[(size_t)ch * (KB/2)];
    for (int i = tid; i < KB/2; i += 1024) g[i] = sh[i];
}

// ------ per-channel exclusive scan: packed u16 hist -> u32 CDF ------
__global__ void scan_kernel(const unsigned int* __restrict__ packed,
                            unsigned int* __restrict__ cdf,
                            const unsigned int* __restrict__ zero) {
    const int ch = blockIdx.x;
    const unsigned int* hp = packed + (size_t)ch * (KB/2);
    unsigned int* cp = cdf + (size_t)ch * KB;
    const int tid = threadIdx.x;         // 1024 threads
    const int lane = tid & 31, wid = tid >> 5;
    __shared__ unsigned int wsum[32];
    __shared__ unsigned int btot;
    unsigned int carry = 0;
    #pragma unroll
    for (int tile = 0; tile < 4; tile++) {
        const int wbase = tile * 8192 + tid * 8;
        uint4 a0 = *(const uint4*)&hp[wbase + 0];
        uint4 a1 = *(const uint4*)&hp[wbase + 4];
        unsigned int wv[8] = {a0.x,a0.y,a0.z,a0.w, a1.x,a1.y,a1.z,a1.w};
        unsigned int e[16];
        #pragma unroll
        for (int i = 0; i < 8; i++) { e[2*i] = wv[i] & 0xffffu; e[2*i+1] = wv[i] >> 16; }
        if (zero && tile == 2 && tid == 0) e[0] += zero[ch];  // bin 32768
        unsigned int tsum = 0;
        #pragma unroll
        for (int i = 0; i < 16; i++) tsum += e[i];
        unsigned int inc = tsum;
        #pragma unroll
        for (int o = 1; o < 32; o <<= 1) {
            unsigned int nv = __shfl_up_sync(0xffffffffu, inc, o);
            if (lane >= o) inc += nv;
        }
        if (lane == 31) wsum[wid] = inc;
        __syncthreads();
        if (wid == 0) {
            unsigned int v0 = wsum[lane];
            unsigned int inc2 = v0;
            #pragma unroll
            for (int o = 1; o < 32; o <<= 1) {
                unsigned int nv = __shfl_up_sync(0xffffffffu, inc2, o);
                if (lane >= o) inc2 += nv;
            }
            wsum[lane] = inc2 - v0;
            if (lane == 31) btot = inc2;
        }
        __syncthreads();
        unsigned int run = carry + wsum[wid] + (inc - tsum);
        unsigned int o_[16];
        #pragma unroll
        for (int i = 0; i < 16; i++) { o_[i] = run; run += e[i]; }
        const int obase = tile * 16384 + tid * 16;
        *(uint4*)&cp[obase + 0]  = make_uint4(o_[0], o_[1], o_[2], o_[3]);
        *(uint4*)&cp[obase + 4]  = make_uint4(o_[4], o_[5], o_[6], o_[7]);
        *(uint4*)&cp[obase + 8]  = make_uint4(o_[8], o_[9], o_[10], o_[11]);
        *(uint4*)&cp[obase + 12] = make_uint4(o_[12], o_[13], o_[14], o_[15]);
        carry += btot;
        __syncthreads();
    }
}

// ------- counting-sort writeout (store-only: imbalance-benign) -------
__global__ void writeout_kernel(const unsigned int* __restrict__ cdf,
                                float* __restrict__ sorted, unsigned int seglen) {
    const int ch  = blockIdx.y;
    const int lane = threadIdx.x & 31, wid = threadIdx.x >> 5;
    const int b0 = blockIdx.x * 256 + wid * 32;
    const unsigned int* __restrict__ cum = cdf + (size_t)ch * KB;
    float* __restrict__ outp = sorted + (size_t)ch * seglen;
    const int b = b0 + lane;
    unsigned int p0v = cum[b];
    unsigned int p1v = (b == KB - 1) ? seglen : cum[b + 1];
    for (int k = 0; k < 32; k++) {
        unsigned int p0 = __shfl_sync(0xffffffffu, p0v, k);
        unsigned int p1 = __shfl_sync(0xffffffffu, p1v, k);
        if (p1 > p0) {
            float v = key2f((unsigned int)(b0 + k));
            for (unsigned int p = p0 + lane; p < p1; p += 32) outp[p] = v;
        }
    }
}

// ------- hist loss: position-parallel streaming (balanced, coalesced) -------
__global__ void hist_loss_kernel() {
    const unsigned int t = blockIdx.x * 256u + threadIdx.x;     // one float4 per thread
    const unsigned int base = t * 4u;
    const unsigned int c = base >> 18;          // / SS
    const unsigned int i = base & (SS - 1);
    const float step = (float)(MM - 1) / (float)(SS - 1);
    float4 sv = *(const float4*)&g_src_sorted[base];
    const float* __restrict__ refq = &g_ref_sorted[(size_t)c * MM];
    float e[4] = {sv.x, sv.y, sv.z, sv.w};
    float fsum = 0.f;
    #pragma unroll
    for (int j = 0; j < 4; j++) {
        float pos = step * (float)(i + j);
        int lo = (int)pos;
        float w = pos - (float)lo;
        int hi = lo + (w > 0.f ? 1 : 0);
        if (hi > MM - 1) hi = MM - 1;
        float r = refq[lo] * (1.0f - w) + refq[hi] * w;
        float d = e[j] - r;
        fsum = fmaf(d, d, fsum);
    }
    block_add((double)fsum, &g_accum[2]);
}

// ------ gram: per-batch F F^T, smem-tiled, FFMA2, forced 4 blocks/SM ------
#define GK 1024
#define GC 128
__global__ void __launch_bounds__(256, 4) gram_kernel(const float* __restrict__ feat) {
    __shared__ float tile[GC][68];
    const int n = blockIdx.y;
    const int base = blockIdx.x * GK;
    const int tid = threadIdx.x;
    const int r0 = (tid / 16) * 4, c0 = (tid % 16) * 4;
    unsigned long long acc01[4] = {0,0,0,0};
    unsigned long long acc23[4] = {0,0,0,0};
    for (int cb = 0; cb < GK; cb += GC) {
        __syncthreads();
        #pragma unroll
        for (int it = 0; it < 32; it++) {
            int li = it * 256 + tid;
            int ch = li >> 7, k = li & 127;
            tile[k][ch] = feat[(unsigned int)(n*64 + ch) * SS + base + cb + k];
        }
        __syncthreads();
        #pragma unroll 4
        for (int k = 0; k < GC; k++) {
            float4 a = *(const float4*)&tile[k][r0];
            unsigned long long b01 = *(const unsigned long long*)&tile[k][c0];
            unsigned long long b23 = *(const unsigned long long*)&tile[k][c0 + 2];
            float ae[4] = {a.x, a.y, a.z, a.w};
            #pragma unroll
            for (int i = 0; i < 4; i++) {
                unsigned long long aa = pk2(ae[i], ae[i]);
                acc01[i] = fma2(aa, b01, acc01[i]);
                acc23[i] = fma2(aa, b23, acc23[i]);
            }
        }
    }
    #pragma unroll
    for (int i = 0; i < 4; i++) {
        float f0, f1, f2, f3;
        upk2(acc01[i], f0, f1);
        upk2(acc23[i], f2, f3);
        float* gg = &g_gram[n*4096 + (r0 + i)*64 + c0];
        atomicAdd(&gg[0], f0);
        atomicAdd(&gg[1], f1);
        atomicAdd(&gg[2], f2);
        atomicAdd(&gg[3], f3);
    }
}

// ---------------- style loss ----------------
__global__ void style_kernel(const float* __restrict__ tgt) {
    int i = blockIdx.x * 256 + threadIdx.x;
    double d = 0.0;
    if (i < BN*CO*CO) {
        float g = g_gram[i] * (1.0f / ((float)CO * HH * WW));
        float df = g - tgt[i];
        d = (double)df * (double)df;
    }
    block_add(d, &g_accum[1]);
}

// ---------------- finalize ----------------
__global__ void finalize_kernel(float* __restrict__ out) {
    if (threadIdx.x == 0) {
        out[NCS + 0] = (float)(g_accum[0] / (double)NCS);
        out[NCS + 1] = (float)(g_accum[1] / (double)(BN*CO*CO));
        out[NCS + 2] = (float)(g_accum[2] / (double)NCS);
    }
}

// ---------------- launch ----------------
extern "C" void kernel_launch(void* const* d_in, const int* in_sizes, int n_in,
                              void* d_out, int out_size) {
    const float* img  = (const float*)d_in[0];
    const float* w    = (const float*)d_in[1];
    const float* b    = (const float*)d_in[2];
    const float* ct   = (const float*)d_in[3];
    const float* stg  = (const float*)d_in[4];
    const float* hist = (const float*)d_in[5];
    float* out = (float*)d_out;

    void *p_hsp, *p_hrp, *p_cs, *p_cr, *p_z, *p_ss, *p_rs;
    cudaGetSymbolAddress(&p_hsp, g_hist_src_p);
    cudaGetSymbolAddress(&p_hrp, g_hist_ref_p);
    cudaGetSymbolAddress(&p_cs,  g_cdf_src);
    cudaGetSymbolAddress(&p_cr,  g_cdf_ref);
    cudaGetSymbolAddress(&p_z,   g_zero);
    cudaGetSymbolAddress(&p_ss,  g_src_sorted);
    cudaGetSymbolAddress(&p_rs,  g_ref_sorted);

    cudaFuncSetAttribute(src_hist_kernel, cudaFuncAttributeMaxDynamicSharedMemorySize, 131072);
    cudaFuncSetAttribute(ref_hist_kernel, cudaFuncAttributeMaxDynamicSharedMemorySize, 131072);

    init_kernel<<<64, 256>>>();

    dim3 cgrid(WW/32, HH/8, BN), cblk(32, 8);
    conv_kernel<<<cgrid, cblk>>>(img, w, b, ct, out);

    src_hist_kernel<<<NC, 1024, 131072>>>((const float4*)out);

    gram_kernel<<<dim3(SS/GK, BN), 256>>>(out);

    ref_hist_kernel<<<NC, 1024, 131072>>>((const float4*)hist);

    scan_kernel<<<NC, 1024>>>((const unsigned int*)p_hsp, (unsigned int*)p_cs,
                              (const unsigned int*)p_z);
    scan_kernel<<<NC, 1024>>>((const unsigned int*)p_hrp, (unsigned int*)p_cr,
                              (const unsigned int*)0);

    writeout_kernel<<<dim3(KB/256, NC), 256>>>((const unsigned int*)p_cr, (float*)p_rs, (unsigned int)MM);
    writeout_kernel<<<dim3(KB/256, NC), 256>>>((const unsigned int*)p_cs, (float*)p_ss, (unsigned int)SS);

    style_kernel<<<(BN*CO*CO + 255)/256, 256>>>(stg);

    hist_loss_kernel<<<NCS/1024, 256>>>();

    finalize_kernel<<<1, 32>>>(out);
    (void)in_sizes; (void)n_in; (void)out_size;
}

// round 11
// speedup vs baseline: 1.2959x; 1.2959x over previous
#include <cuda_runtime.h>
#include <cuda_bf16.h>

#define BN   4
#define CIN  3
#define CO   64
#define HH   512
#define WW   512
#define SS   (HH*WW)        /* 262144 = 2^18 */
#define NC   (BN*CO)        /* 256 */
#define HR   448
#define MM   (HR*HR)        /* 200704 */
#define NCS  (NC*SS)        /* 67108864 */
#define NCM  (NC*MM)        /* 51380224 */
#define KB   65536          /* bins per channel (16-bit sortable key) */

// ---------------- static device scratch (no runtime allocation) ----------------
__device__ unsigned int   g_hist_src_p[NC*KB/2];  // packed u16 counts (32 MB)
__device__ unsigned int   g_hist_ref_p[NC*KB/2];  // packed u16 counts (32 MB)
__device__ unsigned int   g_cdf_src[NC*KB];       // u32 exclusive CDF (64 MB)
__device__ unsigned int   g_cdf_ref[NC*KB];       // u32 exclusive CDF (64 MB)
__device__ unsigned int   g_zero[NC];             // oversized zero-bin counts
__device__ unsigned short g_src_sorted[NCS];      // 134 MB sorted src keys (u16)
__device__ unsigned short g_ref_sorted[NCM];      // 100 MB sorted ref keys (u16)
__device__ double         g_accum[3];             // content, style, hist sums
__device__ float          g_gram[BN*CO*CO];

// ---------------- helpers ----------------
__device__ __forceinline__ unsigned int f2s(float x) {
    unsigned int u = __float_as_uint(x);
    return (u & 0x80000000u) ? ~u : (u | 0x80000000u);
}
__device__ __forceinline__ float s2f(unsigned int k) {
    unsigned int u = (k & 0x80000000u) ? (k ^ 0x80000000u) : ~k;
    return __uint_as_float(u);
}
__device__ __forceinline__ float key2f(unsigned int k16) {
    return s2f((k16 << 16) | 0x8000u);
}

// packed f32x2 (FFMA2) helpers
__device__ __forceinline__ unsigned long long pk2(float lo, float hi) {
    unsigned long long r;
    asm("mov.b64 %0, {%1, %2};" : "=l"(r) : "f"(lo), "f"(hi));
    return r;
}
__device__ __forceinline__ void upk2(unsigned long long v, float& lo, float& hi) {
    asm("mov.b64 {%0, %1}, %2;" : "=f"(lo), "=f"(hi) : "l"(v));
}
__device__ __forceinline__ unsigned long long fma2(unsigned long long a,
                                                   unsigned long long b,
                                                   unsigned long long c) {
    unsigned long long d;
    asm("fma.rn.f32x2 %0, %1, %2, %3;" : "=l"(d) : "l"(a), "l"(b), "l"(c));
    return d;
}

__device__ __forceinline__ void block_add(double v, double* target) {
    __shared__ double sh[8];
    int tid  = threadIdx.x + threadIdx.y * blockDim.x;
    int lane = tid & 31, wid = tid >> 5;
    int nwarps = (blockDim.x * blockDim.y + 31) >> 5;
    #pragma unroll
    for (int o = 16; o > 0; o >>= 1) v += __shfl_down_sync(0xffffffffu, v, o);
    if (lane == 0) sh[wid] = v;
    __syncthreads();
    if (wid == 0) {
        v = (lane < nwarps) ? sh[lane] : 0.0;
        #pragma unroll
        for (int o = 4; o > 0; o >>= 1) v += __shfl_down_sync(0xffffffffu, v, o);
        if (lane == 0) atomicAdd(target, v);
    }
}

// ---------------- init ----------------
__global__ void init_kernel() {
    int i = blockIdx.x * 256 + threadIdx.x;
    if (i < 3) g_accum[i] = 0.0;
    if (i < BN*CO*CO) g_gram[i] = 0.0f;
}

// ------ conv + bias + relu + content-loss (fused, FFMA2 inner) ------
__global__ void conv_kernel(const float* __restrict__ img, const float* __restrict__ w,
                            const float* __restrict__ b,   const float* __restrict__ ct,
                            float* __restrict__ out) {
    __shared__ float sin[3][10][34];
    __shared__ float sw[27][64];
    __shared__ float sb[64];
    const int n  = blockIdx.z;
    const int x0 = blockIdx.x * 32;
    const int y0 = blockIdx.y * 8;
    const int tid = threadIdx.y * 32 + threadIdx.x;

    for (int i = tid; i < 1728; i += 256) { int co = i / 27, tap = i % 27; sw[tap][co] = w[i]; }
    if (tid < 64) sb[tid] = b[tid];

    const float mean[3] = {0.485f, 0.456f, 0.406f};
    const float istd[3] = {1.f/0.229f, 1.f/0.224f, 1.f/0.225f};
    #pragma unroll
    for (int c = 0; c < 3; c++) {
        for (int i = tid; i < 340; i += 256) {
            int r = i / 34, cc = i % 34;
            int gy = y0 + r - 1, gx = x0 + cc - 1;
            float v = 0.f;
            if (gy >= 0 && gy < HH && gx >= 0 && gx < WW)
                v = (img[((n*3 + c)*HH + gy)*WW + gx] - mean[c]) * istd[c];
            sin[c][r][cc] = v;
        }
    }
    __syncthreads();

    const int px = threadIdx.x, py = threadIdx.y;
    unsigned long long v2[27];
    #pragma unroll
    for (int c = 0; c < 3; c++)
        #pragma unroll
        for (int ky = 0; ky < 3; ky++)
            #pragma unroll
            for (int kx = 0; kx < 3; kx++) {
                float vv = sin[c][py + ky][px + kx];
                v2[c*9 + ky*3 + kx] = pk2(vv, vv);
            }

    const int y = y0 + py, x = x0 + px;
    float fsum = 0.f;
    #pragma unroll
    for (int cb = 0; cb < 64; cb += 16) {
        unsigned long long acc2[8];
        #pragma unroll
        for (int j = 0; j < 8; j++) acc2[j] = *(const unsigned long long*)&sb[cb + 2*j];
        #pragma unroll
        for (int t2 = 0; t2 < 27; t2++) {
            unsigned long long vv = v2[t2];
            #pragma unroll
            for (int j = 0; j < 8; j++)
                acc2[j] = fma2(vv, *(const unsigned long long*)&sw[t2][cb + 2*j], acc2[j]);
        }
        #pragma unroll
        for (int j = 0; j < 8; j++) {
            float f0, f1;
            upk2(acc2[j], f0, f1);
            f0 = f0 > 0.f ? f0 : 0.f;
            f1 = f1 > 0.f ? f1 : 0.f;
            unsigned int ch0 = (unsigned int)(n*64 + cb + 2*j);
            unsigned int oi0 = ch0 * SS + (unsigned int)y * WW + x;
            out[oi0]      = f0;
            out[oi0 + SS] = f1;
            float d0 = f0 - ct[oi0];
            float d1 = f1 - ct[oi0 + SS];
            fsum = fmaf(d0, d0, fsum);
            fsum = fmaf(d1, d1, fsum);
        }
    }
    block_add((double)fsum, &g_accum[0]);
}

// ------ per-channel histogram of feat: plain smem atomics (R9 version) ------
__global__ void __launch_bounds__(1024) src_hist_kernel(const float4* __restrict__ feat) {
    extern __shared__ unsigned int sh[];  // KB/2 = 32768 words
    __shared__ unsigned int zwarp[32];
    const int ch  = blockIdx.x;
    const int tid = threadIdx.x;
    const int lane = tid & 31, wid = tid >> 5;
    for (int i = tid; i < KB/2; i += 1024) sh[i] = 0;
    __syncthreads();

    const float4* p = feat + (size_t)ch * (SS/4);
    unsigned int zc = 0;
    for (int i = tid; i < SS/4; i += 1024) {
        float4 v = p[i];
        float e[4] = {v.x, v.y, v.z, v.w};
        #pragma unroll
        for (int j = 0; j < 4; j++) {
            float f = e[j];
            if (f == 0.f) { zc++; }
            else {
                unsigned int k = f2s(f) >> 16;
                atomicAdd(&sh[k >> 1], 1u << ((k & 1) * 16));
            }
        }
    }
    #pragma unroll
    for (int o = 16; o > 0; o >>= 1) zc += __shfl_down_sync(0xffffffffu, zc, o);
    if (lane == 0) zwarp[wid] = zc;
    __syncthreads();
    if (tid == 0) {
        unsigned int s = 0;
        #pragma unroll
        for (int i = 0; i < 32; i++) s += zwarp[i];
        g_zero[ch] = s;
    }

    unsigned int* g = &g_hist_src_p[(size_t)ch * (KB/2)];
    for (int i = tid; i < KB/2; i += 1024) g[i] = sh[i];
}

// ------ per-channel histogram of ref target ------
__global__ void __launch_bounds__(1024) ref_hist_kernel(const float4* __restrict__ vals) {
    extern __shared__ unsigned int sh[];
    const int ch  = blockIdx.x;
    const int tid = threadIdx.x;
    for (int i = tid; i < KB/2; i += 1024) sh[i] = 0;
    __syncthreads();

    const float4* p = vals + (size_t)ch * (MM/4);
    for (int i = tid; i < MM/4; i += 1024) {
        float4 v = p[i];
        float e[4] = {v.x, v.y, v.z, v.w};
        #pragma unroll
        for (int j = 0; j < 4; j++) {
            unsigned int k = f2s(e[j]) >> 16;
            atomicAdd(&sh[k >> 1], 1u << ((k & 1) * 16));
        }
    }
    __syncthreads();

    unsigned int* g = &g_hist_ref_p[(size_t)ch * (KB/2)];
    for (int i = tid; i < KB/2; i += 1024) g[i] = sh[i];
}

// ------ per-channel exclusive scan: packed u16 hist -> u32 CDF ------
__global__ void scan_kernel(const unsigned int* __restrict__ packed,
                            unsigned int* __restrict__ cdf,
                            const unsigned int* __restrict__ zero) {
    const int ch = blockIdx.x;
    const unsigned int* hp = packed + (size_t)ch * (KB/2);
    unsigned int* cp = cdf + (size_t)ch * KB;
    const int tid = threadIdx.x;         // 1024 threads
    const int lane = tid & 31, wid = tid >> 5;
    __shared__ unsigned int wsum[32];
    __shared__ unsigned int btot;
    unsigned int carry = 0;
    #pragma unroll
    for (int tile = 0; tile < 4; tile++) {
        const int wbase = tile * 8192 + tid * 8;
        uint4 a0 = *(const uint4*)&hp[wbase + 0];
        uint4 a1 = *(const uint4*)&hp[wbase + 4];
        unsigned int wv[8] = {a0.x,a0.y,a0.z,a0.w, a1.x,a1.y,a1.z,a1.w};
        unsigned int e[16];
        #pragma unroll
        for (int i = 0; i < 8; i++) { e[2*i] = wv[i] & 0xffffu; e[2*i+1] = wv[i] >> 16; }
        if (zero && tile == 2 && tid == 0) e[0] += zero[ch];  // bin 32768
        unsigned int tsum = 0;
        #pragma unroll
        for (int i = 0; i < 16; i++) tsum += e[i];
        unsigned int inc = tsum;
        #pragma unroll
        for (int o = 1; o < 32; o <<= 1) {
            unsigned int nv = __shfl_up_sync(0xffffffffu, inc, o);
            if (lane >= o) inc += nv;
        }
        if (lane == 31) wsum[wid] = inc;
        __syncthreads();
        if (wid == 0) {
            unsigned int v0 = wsum[lane];
            unsigned int inc2 = v0;
            #pragma unroll
            for (int o = 1; o < 32; o <<= 1) {
                unsigned int nv = __shfl_up_sync(0xffffffffu, inc2, o);
                if (lane >= o) inc2 += nv;
            }
            wsum[lane] = inc2 - v0;
            if (lane == 31) btot = inc2;
        }
        __syncthreads();
        unsigned int run = carry + wsum[wid] + (inc - tsum);
        unsigned int o_[16];
        #pragma unroll
        for (int i = 0; i < 16; i++) { o_[i] = run; run += e[i]; }
        const int obase = tile * 16384 + tid * 16;
        *(uint4*)&cp[obase + 0]  = make_uint4(o_[0], o_[1], o_[2], o_[3]);
        *(uint4*)&cp[obase + 4]  = make_uint4(o_[4], o_[5], o_[6], o_[7]);
        *(uint4*)&cp[obase + 8]  = make_uint4(o_[8], o_[9], o_[10], o_[11]);
        *(uint4*)&cp[obase + 12] = make_uint4(o_[12], o_[13], o_[14], o_[15]);
        carry += btot;
        __syncthreads();
    }
}

// ------- counting-sort writeout of u16 keys (store-only: imbalance-benign) -------
__global__ void writeout_kernel(const unsigned int* __restrict__ cdf,
                                unsigned short* __restrict__ sorted, unsigned int seglen) {
    const int ch  = blockIdx.y;
    const int lane = threadIdx.x & 31, wid = threadIdx.x >> 5;
    const int b0 = blockIdx.x * 256 + wid * 32;
    const unsigned int* __restrict__ cum = cdf + (size_t)ch * KB;
    unsigned short* __restrict__ outp = sorted + (size_t)ch * seglen;
    const int b = b0 + lane;
    unsigned int p0v = cum[b];
    unsigned int p1v = (b == KB - 1) ? seglen : cum[b + 1];
    for (int k = 0; k < 32; k++) {
        unsigned int p0 = __shfl_sync(0xffffffffu, p0v, k);
        unsigned int p1 = __shfl_sync(0xffffffffu, p1v, k);
        if (p1 > p0) {
            unsigned short kv = (unsigned short)(b0 + k);
            for (unsigned int p = p0 + lane; p < p1; p += 32) outp[p] = kv;
        }
    }
}

// ------- hist loss: position-parallel streaming over u16 keys -------
__global__ void hist_loss_kernel() {
    const unsigned int t = blockIdx.x * 256u + threadIdx.x;   // 8 keys per thread
    const unsigned int base = t * 8u;
    const unsigned int c = base >> 18;          // / SS
    const unsigned int i = base & (SS - 1);
    const float step = (float)(MM - 1) / (float)(SS - 1);
    uint4 kv = *(const uint4*)&g_src_sorted[base];
    const unsigned short* __restrict__ refq = &g_ref_sorted[(size_t)c * MM];
    unsigned int kw[4] = {kv.x, kv.y, kv.z, kv.w};
    float fsum = 0.f;
    #pragma unroll
    for (int j = 0; j < 8; j++) {
        unsigned int k16 = (kw[j >> 1] >> ((j & 1) * 16)) & 0xffffu;
        float v = key2f(k16);
        float pos = step * (float)(i + j);
        int lo = (int)pos;
        float w = pos - (float)lo;
        int hi = lo + (w > 0.f ? 1 : 0);
        if (hi > MM - 1) hi = MM - 1;
        float rlo = key2f((unsigned int)refq[lo]);
        float rhi = key2f((unsigned int)refq[hi]);
        float r = rlo * (1.0f - w) + rhi * w;
        float d = v - r;
        fsum = fmaf(d, d, fsum);
    }
    block_add((double)fsum, &g_accum[2]);
}

// ------ gram: per-batch F F^T, smem-tiled, FFMA2, forced 4 blocks/SM ------
#define GK 1024
#define GC 128
__global__ void __launch_bounds__(256, 4) gram_kernel(const float* __restrict__ feat) {
    __shared__ float tile[GC][68];
    const int n = blockIdx.y;
    const int base = blockIdx.x * GK;
    const int tid = threadIdx.x;
    const int r0 = (tid / 16) * 4, c0 = (tid % 16) * 4;
    unsigned long long acc01[4] = {0,0,0,0};
    unsigned long long acc23[4] = {0,0,0,0};
    for (int cb = 0; cb < GK; cb += GC) {
        __syncthreads();
        #pragma unroll
        for (int it = 0; it < 32; it++) {
            int li = it * 256 + tid;
            int ch = li >> 7, k = li & 127;
            tile[k][ch] = feat[(unsigned int)(n*64 + ch) * SS + base + cb + k];
        }
        __syncthreads();
        #pragma unroll 4
        for (int k = 0; k < GC; k++) {
            float4 a = *(const float4*)&tile[k][r0];
            unsigned long long b01 = *(const unsigned long long*)&tile[k][c0];
            unsigned long long b23 = *(const unsigned long long*)&tile[k][c0 + 2];
            float ae[4] = {a.x, a.y, a.z, a.w};
            #pragma unroll
            for (int i = 0; i < 4; i++) {
                unsigned long long aa = pk2(ae[i], ae[i]);
                acc01[i] = fma2(aa, b01, acc01[i]);
                acc23[i] = fma2(aa, b23, acc23[i]);
            }
        }
    }
    #pragma unroll
    for (int i = 0; i < 4; i++) {
        float f0, f1, f2, f3;
        upk2(acc01[i], f0, f1);
        upk2(acc23[i], f2, f3);
        float* gg = &g_gram[n*4096 + (r0 + i)*64 + c0];
        atomicAdd(&gg[0], f0);
        atomicAdd(&gg[1], f1);
        atomicAdd(&gg[2], f2);
        atomicAdd(&gg[3], f3);
    }
}

// ---------------- style loss ----------------
__global__ void style_kernel(const float* __restrict__ tgt) {
    int i = blockIdx.x * 256 + threadIdx.x;
    double d = 0.0;
    if (i < BN*CO*CO) {
        float g = g_gram[i] * (1.0f / ((float)CO * HH * WW));
        float df = g - tgt[i];
        d = (double)df * (double)df;
    }
    block_add(d, &g_accum[1]);
}

// ---------------- finalize ----------------
__global__ void finalize_kernel(float* __restrict__ out) {
    if (threadIdx.x == 0) {
        out[NCS + 0] = (float)(g_accum[0] / (double)NCS);
        out[NCS + 1] = (float)(g_accum[1] / (double)(BN*CO*CO));
        out[NCS + 2] = (float)(g_accum[2] / (double)NCS);
    }
}

// ---------------- launch ----------------
extern "C" void kernel_launch(void* const* d_in, const int* in_sizes, int n_in,
                              void* d_out, int out_size) {
    const float* img  = (const float*)d_in[0];
    const float* w    = (const float*)d_in[1];
    const float* b    = (const float*)d_in[2];
    const float* ct   = (const float*)d_in[3];
    const float* stg  = (const float*)d_in[4];
    const float* hist = (const float*)d_in[5];
    float* out = (float*)d_out;

    void *p_hsp, *p_hrp, *p_cs, *p_cr, *p_z, *p_ss, *p_rs;
    cudaGetSymbolAddress(&p_hsp, g_hist_src_p);
    cudaGetSymbolAddress(&p_hrp, g_hist_ref_p);
    cudaGetSymbolAddress(&p_cs,  g_cdf_src);
    cudaGetSymbolAddress(&p_cr,  g_cdf_ref);
    cudaGetSymbolAddress(&p_z,   g_zero);
    cudaGetSymbolAddress(&p_ss,  g_src_sorted);
    cudaGetSymbolAddress(&p_rs,  g_ref_sorted);

    cudaFuncSetAttribute(src_hist_kernel, cudaFuncAttributeMaxDynamicSharedMemorySize, 131072);
    cudaFuncSetAttribute(ref_hist_kernel, cudaFuncAttributeMaxDynamicSharedMemorySize, 131072);

    init_kernel<<<64, 256>>>();

    dim3 cgrid(WW/32, HH/8, BN), cblk(32, 8);
    conv_kernel<<<cgrid, cblk>>>(img, w, b, ct, out);

    gram_kernel<<<dim3(SS/GK, BN), 256>>>(out);

    // src_hist in the profiled (4th) launch slot — its cost is the remaining unknown
    src_hist_kernel<<<NC, 1024, 131072>>>((const float4*)out);

    ref_hist_kernel<<<NC, 1024, 131072>>>((const float4*)hist);

    scan_kernel<<<NC, 1024>>>((const unsigned int*)p_hsp, (unsigned int*)p_cs,
                              (const unsigned int*)p_z);
    scan_kernel<<<NC, 1024>>>((const unsigned int*)p_hrp, (unsigned int*)p_cr,
                              (const unsigned int*)0);

    writeout_kernel<<<dim3(KB/256, NC), 256>>>((const unsigned int*)p_cr, (unsigned short*)p_rs, (unsigned int)MM);
    writeout_kernel<<<dim3(KB/256, NC), 256>>>((const unsigned int*)p_cs, (unsigned short*)p_ss, (unsigned int)SS);

    style_kernel<<<(BN*CO*CO + 255)/256, 256>>>(stg);

    hist_loss_kernel<<<NCS/2048, 256>>>();

    finalize_kernel<<<1, 32>>>(out);
    (void)in_sizes; (void)n_in; (void)out_size;
}

// round 12
// speedup vs baseline: 1.3008x; 1.0038x over previous
#include <cuda_runtime.h>
#include <cuda_bf16.h>

#define BN   4
#define CIN  3
#define CO   64
#define HH   512
#define WW   512
#define SS   (HH*WW)        /* 262144 = 2^18 */
#define NC   (BN*CO)        /* 256 */
#define HR   448
#define MM   (HR*HR)        /* 200704 */
#define NCS  (NC*SS)        /* 67108864 */
#define NCM  (NC*MM)        /* 51380224 */
#define KB   65536          /* bins per channel (16-bit sortable key) */

// ---------------- static device scratch (no runtime allocation) ----------------
__device__ unsigned int   g_hist_src_p[NC*KB/2];  // packed u16 counts (32 MB)
__device__ unsigned int   g_hist_ref_p[NC*KB/2];  // packed u16 counts (32 MB)
__device__ unsigned int   g_cdf_src[NC*KB];       // u32 exclusive CDF (64 MB)
__device__ unsigned int   g_cdf_ref[NC*KB];       // u32 exclusive CDF (64 MB)
__device__ unsigned int   g_zero[NC];             // oversized zero-bin counts
__device__ unsigned short g_src_sorted[NCS];      // 134 MB sorted src keys (u16)
__device__ unsigned short g_ref_sorted[NCM];      // 100 MB sorted ref keys (u16)
__device__ double         g_accum[3];             // content, style, hist sums
__device__ float          g_gram[BN*CO*CO];

// ---------------- helpers ----------------
__device__ __forceinline__ unsigned int f2s(float x) {
    unsigned int u = __float_as_uint(x);
    return (u & 0x80000000u) ? ~u : (u | 0x80000000u);
}
__device__ __forceinline__ float s2f(unsigned int k) {
    unsigned int u = (k & 0x80000000u) ? (k ^ 0x80000000u) : ~k;
    return __uint_as_float(u);
}
__device__ __forceinline__ float key2f(unsigned int k16) {
    return s2f((k16 << 16) | 0x8000u);
}

// packed f32x2 (FFMA2) helpers
__device__ __forceinline__ unsigned long long pk2(float lo, float hi) {
    unsigned long long r;
    asm("mov.b64 %0, {%1, %2};" : "=l"(r) : "f"(lo), "f"(hi));
    return r;
}
__device__ __forceinline__ void upk2(unsigned long long v, float& lo, float& hi) {
    asm("mov.b64 {%0, %1}, %2;" : "=f"(lo), "=f"(hi) : "l"(v));
}
__device__ __forceinline__ unsigned long long fma2(unsigned long long a,
                                                   unsigned long long b,
                                                   unsigned long long c) {
    unsigned long long d;
    asm("fma.rn.f32x2 %0, %1, %2, %3;" : "=l"(d) : "l"(a), "l"(b), "l"(c));
    return d;
}

__device__ __forceinline__ void block_add(double v, double* target) {
    __shared__ double sh[8];
    int tid  = threadIdx.x + threadIdx.y * blockDim.x;
    int lane = tid & 31, wid = tid >> 5;
    int nwarps = (blockDim.x * blockDim.y + 31) >> 5;
    #pragma unroll
    for (int o = 16; o > 0; o >>= 1) v += __shfl_down_sync(0xffffffffu, v, o);
    if (lane == 0) sh[wid] = v;
    __syncthreads();
    if (wid == 0) {
        v = (lane < nwarps) ? sh[lane] : 0.0;
        #pragma unroll
        for (int o = 4; o > 0; o >>= 1) v += __shfl_down_sync(0xffffffffu, v, o);
        if (lane == 0) atomicAdd(target, v);
    }
}

// ---------------- init ----------------
__global__ void init_kernel() {
    int i = blockIdx.x * 256 + threadIdx.x;
    if (i < 3) g_accum[i] = 0.0;
    if (i < BN*CO*CO) g_gram[i] = 0.0f;
}

// ------ conv + bias + relu + content-loss (fused; low register pressure) ------
__global__ void conv_kernel(const float* __restrict__ img, const float* __restrict__ w,
                            const float* __restrict__ b,   const float* __restrict__ ct,
                            float* __restrict__ out) {
    __shared__ float sin[3][10][34];
    __shared__ float sw[27][64];
    __shared__ float sb[64];
    const int n  = blockIdx.z;
    const int x0 = blockIdx.x * 32;
    const int y0 = blockIdx.y * 8;
    const int tid = threadIdx.y * 32 + threadIdx.x;

    for (int i = tid; i < 1728; i += 256) { int co = i / 27, tap = i % 27; sw[tap][co] = w[i]; }
    if (tid < 64) sb[tid] = b[tid];

    const float mean[3] = {0.485f, 0.456f, 0.406f};
    const float istd[3] = {1.f/0.229f, 1.f/0.224f, 1.f/0.225f};
    #pragma unroll
    for (int c = 0; c < 3; c++) {
        for (int i = tid; i < 340; i += 256) {
            int r = i / 34, cc = i % 34;
            int gy = y0 + r - 1, gx = x0 + cc - 1;
            float v = 0.f;
            if (gy >= 0 && gy < HH && gx >= 0 && gx < WW)
                v = (img[((n*3 + c)*HH + gy)*WW + gx] - mean[c]) * istd[c];
            sin[c][r][cc] = v;
        }
    }
    __syncthreads();

    const int px = threadIdx.x, py = threadIdx.y;
    float v[27];                      // 27 regs (not 54 packed)
    #pragma unroll
    for (int c = 0; c < 3; c++)
        #pragma unroll
        for (int ky = 0; ky < 3; ky++)
            #pragma unroll
            for (int kx = 0; kx < 3; kx++)
                v[c*9 + ky*3 + kx] = sin[c][py + ky][px + kx];

    const int y = y0 + py, x = x0 + px;
    float fsum = 0.f;
    #pragma unroll
    for (int cb = 0; cb < 64; cb += 16) {
        unsigned long long acc2[8];
        #pragma unroll
        for (int j = 0; j < 8; j++) acc2[j] = *(const unsigned long long*)&sb[cb + 2*j];
        #pragma unroll
        for (int t2 = 0; t2 < 27; t2++) {
            unsigned long long vv = pk2(v[t2], v[t2]);   // pack per use
            #pragma unroll
            for (int j = 0; j < 8; j++)
                acc2[j] = fma2(vv, *(const unsigned long long*)&sw[t2][cb + 2*j], acc2[j]);
        }
        #pragma unroll
        for (int j = 0; j < 8; j++) {
            float f0, f1;
            upk2(acc2[j], f0, f1);
            f0 = f0 > 0.f ? f0 : 0.f;
            f1 = f1 > 0.f ? f1 : 0.f;
            unsigned int ch0 = (unsigned int)(n*64 + cb + 2*j);
            unsigned int oi0 = ch0 * SS + (unsigned int)y * WW + x;
            out[oi0]      = f0;
            out[oi0 + SS] = f1;
            float d0 = f0 - ct[oi0];
            float d1 = f1 - ct[oi0 + SS];
            fsum = fmaf(d0, d0, fsum);
            fsum = fmaf(d1, d1, fsum);
        }
    }
    block_add((double)fsum, &g_accum[0]);
}

// ------ per-channel histogram of feat: plain smem atomics ------
__global__ void __launch_bounds__(1024) src_hist_kernel(const float4* __restrict__ feat) {
    extern __shared__ unsigned int sh[];  // KB/2 = 32768 words
    __shared__ unsigned int zwarp[32];
    const int ch  = blockIdx.x;
    const int tid = threadIdx.x;
    const int lane = tid & 31, wid = tid >> 5;
    for (int i = tid; i < KB/2; i += 1024) sh[i] = 0;
    __syncthreads();

    const float4* p = feat + (size_t)ch * (SS/4);
    unsigned int zc = 0;
    for (int i = tid; i < SS/4; i += 1024) {
        float4 v = p[i];
        float e[4] = {v.x, v.y, v.z, v.w};
        #pragma unroll
        for (int j = 0; j < 4; j++) {
            float f = e[j];
            if (f == 0.f) { zc++; }
            else {
                unsigned int k = f2s(f) >> 16;
                atomicAdd(&sh[k >> 1], 1u << ((k & 1) * 16));
            }
        }
    }
    #pragma unroll
    for (int o = 16; o > 0; o >>= 1) zc += __shfl_down_sync(0xffffffffu, zc, o);
    if (lane == 0) zwarp[wid] = zc;
    __syncthreads();
    if (tid == 0) {
        unsigned int s = 0;
        #pragma unroll
        for (int i = 0; i < 32; i++) s += zwarp[i];
        g_zero[ch] = s;
    }

    unsigned int* g = &g_hist_src_p[(size_t)ch * (KB/2)];
    for (int i = tid; i < KB/2; i += 1024) g[i] = sh[i];
}

// ------ per-channel histogram of ref target ------
__global__ void __launch_bounds__(1024) ref_hist_kernel(const float4* __restrict__ vals) {
    extern __shared__ unsigned int sh[];
    const int ch  = blockIdx.x;
    const int tid = threadIdx.x;
    for (int i = tid; i < KB/2; i += 1024) sh[i] = 0;
    __syncthreads();

    const float4* p = vals + (size_t)ch * (MM/4);
    for (int i = tid; i < MM/4; i += 1024) {
        float4 v = p[i];
        float e[4] = {v.x, v.y, v.z, v.w};
        #pragma unroll
        for (int j = 0; j < 4; j++) {
            unsigned int k = f2s(e[j]) >> 16;
            atomicAdd(&sh[k >> 1], 1u << ((k & 1) * 16));
        }
    }
    __syncthreads();

    unsigned int* g = &g_hist_ref_p[(size_t)ch * (KB/2)];
    for (int i = tid; i < KB/2; i += 1024) g[i] = sh[i];
}

// ------ per-channel exclusive scan: packed u16 hist -> u32 CDF ------
__global__ void scan_kernel(const unsigned int* __restrict__ packed,
                            unsigned int* __restrict__ cdf,
                            const unsigned int* __restrict__ zero) {
    const int ch = blockIdx.x;
    const unsigned int* hp = packed + (size_t)ch * (KB/2);
    unsigned int* cp = cdf + (size_t)ch * KB;
    const int tid = threadIdx.x;         // 1024 threads
    const int lane = tid & 31, wid = tid >> 5;
    __shared__ unsigned int wsum[32];
    __shared__ unsigned int btot;
    unsigned int carry = 0;
    #pragma unroll
    for (int tile = 0; tile < 4; tile++) {
        const int wbase = tile * 8192 + tid * 8;
        uint4 a0 = *(const uint4*)&hp[wbase + 0];
        uint4 a1 = *(const uint4*)&hp[wbase + 4];
        unsigned int wv[8] = {a0.x,a0.y,a0.z,a0.w, a1.x,a1.y,a1.z,a1.w};
        unsigned int e[16];
        #pragma unroll
        for (int i = 0; i < 8; i++) { e[2*i] = wv[i] & 0xffffu; e[2*i+1] = wv[i] >> 16; }
        if (zero && tile == 2 && tid == 0) e[0] += zero[ch];  // bin 32768
        unsigned int tsum = 0;
        #pragma unroll
        for (int i = 0; i < 16; i++) tsum += e[i];
        unsigned int inc = tsum;
        #pragma unroll
        for (int o = 1; o < 32; o <<= 1) {
            unsigned int nv = __shfl_up_sync(0xffffffffu, inc, o);
            if (lane >= o) inc += nv;
        }
        if (lane == 31) wsum[wid] = inc;
        __syncthreads();
        if (wid == 0) {
            unsigned int v0 = wsum[lane];
            unsigned int inc2 = v0;
            #pragma unroll
            for (int o = 1; o < 32; o <<= 1) {
                unsigned int nv = __shfl_up_sync(0xffffffffu, inc2, o);
                if (lane >= o) inc2 += nv;
            }
            wsum[lane] = inc2 - v0;
            if (lane == 31) btot = inc2;
        }
        __syncthreads();
        unsigned int run = carry + wsum[wid] + (inc - tsum);
        unsigned int o_[16];
        #pragma unroll
        for (int i = 0; i < 16; i++) { o_[i] = run; run += e[i]; }
        const int obase = tile * 16384 + tid * 16;
        *(uint4*)&cp[obase + 0]  = make_uint4(o_[0], o_[1], o_[2], o_[3]);
        *(uint4*)&cp[obase + 4]  = make_uint4(o_[4], o_[5], o_[6], o_[7]);
        *(uint4*)&cp[obase + 8]  = make_uint4(o_[8], o_[9], o_[10], o_[11]);
        *(uint4*)&cp[obase + 12] = make_uint4(o_[12], o_[13], o_[14], o_[15]);
        carry += btot;
        __syncthreads();
    }
}

// ------- counting-sort writeout of u16 keys (store-only: imbalance-benign) -------
__global__ void writeout_kernel(const unsigned int* __restrict__ cdf,
                                unsigned short* __restrict__ sorted, unsigned int seglen) {
    const int ch  = blockIdx.y;
    const int lane = threadIdx.x & 31, wid = threadIdx.x >> 5;
    const int b0 = blockIdx.x * 256 + wid * 32;
    const unsigned int* __restrict__ cum = cdf + (size_t)ch * KB;
    unsigned short* __restrict__ outp = sorted + (size_t)ch * seglen;
    const int b = b0 + lane;
    unsigned int p0v = cum[b];
    unsigned int p1v = (b == KB - 1) ? seglen : cum[b + 1];
    for (int k = 0; k < 32; k++) {
        unsigned int p0 = __shfl_sync(0xffffffffu, p0v, k);
        unsigned int p1 = __shfl_sync(0xffffffffu, p1v, k);
        if (p1 > p0) {
            unsigned short kv = (unsigned short)(b0 + k);
            for (unsigned int p = p0 + lane; p < p1; p += 32) outp[p] = kv;
        }
    }
}

// ------- hist loss: position-parallel streaming over u16 keys -------
__global__ void hist_loss_kernel() {
    const unsigned int t = blockIdx.x * 256u + threadIdx.x;   // 8 keys per thread
    const unsigned int base = t * 8u;
    const unsigned int c = base >> 18;          // / SS
    const unsigned int i = base & (SS - 1);
    const float step = (float)(MM - 1) / (float)(SS - 1);
    uint4 kv = *(const uint4*)&g_src_sorted[base];
    const unsigned short* __restrict__ refq = &g_ref_sorted[(size_t)c * MM];
    unsigned int kw[4] = {kv.x, kv.y, kv.z, kv.w};
    float fsum = 0.f;
    #pragma unroll
    for (int j = 0; j < 8; j++) {
        unsigned int k16 = (kw[j >> 1] >> ((j & 1) * 16)) & 0xffffu;
        float v = key2f(k16);
        float pos = step * (float)(i + j);
        int lo = (int)pos;
        float w = pos - (float)lo;
        int hi = lo + (w > 0.f ? 1 : 0);
        if (hi > MM - 1) hi = MM - 1;
        float rlo = key2f((unsigned int)refq[lo]);
        float rhi = key2f((unsigned int)refq[hi]);
        float r = rlo * (1.0f - w) + rhi * w;
        float d = v - r;
        fsum = fmaf(d, d, fsum);
    }
    block_add((double)fsum, &g_accum[2]);
}

// ------ gram: per-batch F F^T, smem-tiled, FFMA2, forced 4 blocks/SM ------
#define GK 1024
#define GC 128
__global__ void __launch_bounds__(256, 4) gram_kernel(const float* __restrict__ feat) {
    __shared__ float tile[GC][68];
    const int n = blockIdx.y;
    const int base = blockIdx.x * GK;
    const int tid = threadIdx.x;
    const int r0 = (tid / 16) * 4, c0 = (tid % 16) * 4;
    unsigned long long acc01[4] = {0,0,0,0};
    unsigned long long acc23[4] = {0,0,0,0};
    for (int cb = 0; cb < GK; cb += GC) {
        __syncthreads();
        #pragma unroll
        for (int it = 0; it < 32; it++) {
            int li = it * 256 + tid;
            int ch = li >> 7, k = li & 127;
            tile[k][ch] = feat[(unsigned int)(n*64 + ch) * SS + base + cb + k];
        }
        __syncthreads();
        #pragma unroll 4
        for (int k = 0; k < GC; k++) {
            float4 a = *(const float4*)&tile[k][r0];
            float4 bq = *(const float4*)&tile[k][c0];   // one LDS.128
            unsigned long long b01, b23;
            b01 = pk2(bq.x, bq.y);
            b23 = pk2(bq.z, bq.w);
            float ae[4] = {a.x, a.y, a.z, a.w};
            #pragma unroll
            for (int i = 0; i < 4; i++) {
                unsigned long long aa = pk2(ae[i], ae[i]);
                acc01[i] = fma2(aa, b01, acc01[i]);
                acc23[i] = fma2(aa, b23, acc23[i]);
            }
        }
    }
    #pragma unroll
    for (int i = 0; i < 4; i++) {
        float f0, f1, f2, f3;
        upk2(acc01[i], f0, f1);
        upk2(acc23[i], f2, f3);
        float* gg = &g_gram[n*4096 + (r0 + i)*64 + c0];
        atomicAdd(&gg[0], f0);
        atomicAdd(&gg[1], f1);
        atomicAdd(&gg[2], f2);
        atomicAdd(&gg[3], f3);
    }
}

// ---------------- style loss ----------------
__global__ void style_kernel(const float* __restrict__ tgt) {
    int i = blockIdx.x * 256 + threadIdx.x;
    double d = 0.0;
    if (i < BN*CO*CO) {
        float g = g_gram[i] * (1.0f / ((float)CO * HH * WW));
        float df = g - tgt[i];
        d = (double)df * (double)df;
    }
    block_add(d, &g_accum[1]);
}

// ---------------- finalize ----------------
__global__ void finalize_kernel(float* __restrict__ out) {
    if (threadIdx.x == 0) {
        out[NCS + 0] = (float)(g_accum[0] / (double)NCS);
        out[NCS + 1] = (float)(g_accum[1] / (double)(BN*CO*CO));
        out[NCS + 2] = (float)(g_accum[2] / (double)NCS);
    }
}

// ---------------- launch ----------------
extern "C" void kernel_launch(void* const* d_in, const int* in_sizes, int n_in,
                              void* d_out, int out_size) {
    const float* img  = (const float*)d_in[0];
    const float* w    = (const float*)d_in[1];
    const float* b    = (const float*)d_in[2];
    const float* ct   = (const float*)d_in[3];
    const float* stg  = (const float*)d_in[4];
    const float* hist = (const float*)d_in[5];
    float* out = (float*)d_out;

    void *p_hsp, *p_hrp, *p_cs, *p_cr, *p_z, *p_ss, *p_rs;
    cudaGetSymbolAddress(&p_hsp, g_hist_src_p);
    cudaGetSymbolAddress(&p_hrp, g_hist_ref_p);
    cudaGetSymbolAddress(&p_cs,  g_cdf_src);
    cudaGetSymbolAddress(&p_cr,  g_cdf_ref);
    cudaGetSymbolAddress(&p_z,   g_zero);
    cudaGetSymbolAddress(&p_ss,  g_src_sorted);
    cudaGetSymbolAddress(&p_rs,  g_ref_sorted);

    cudaFuncSetAttribute(src_hist_kernel, cudaFuncAttributeMaxDynamicSharedMemorySize, 131072);
    cudaFuncSetAttribute(ref_hist_kernel, cudaFuncAttributeMaxDynamicSharedMemorySize, 131072);

    // launches 1-3: independent of conv, shifts conv into the profiled 4th slot
    init_kernel<<<64, 256>>>();
    ref_hist_kernel<<<NC, 1024, 131072>>>((const float4*)hist);
    scan_kernel<<<NC, 1024>>>((const unsigned int*)p_hrp, (unsigned int*)p_cr,
                              (const unsigned int*)0);

    dim3 cgrid(WW/32, HH/8, BN), cblk(32, 8);
    conv_kernel<<<cgrid, cblk>>>(img, w, b, ct, out);   // 4th launch -> profiled

    src_hist_kernel<<<NC, 1024, 131072>>>((const float4*)out);
    gram_kernel<<<dim3(SS/GK, BN), 256>>>(out);

    scan_kernel<<<NC, 1024>>>((const unsigned int*)p_hsp, (unsigned int*)p_cs,
                              (const unsigned int*)p_z);

    writeout_kernel<<<dim3(KB/256, NC), 256>>>((const unsigned int*)p_cr, (unsigned short*)p_rs, (unsigned int)MM);
    writeout_kernel<<<dim3(KB/256, NC), 256>>>((const unsigned int*)p_cs, (unsigned short*)p_ss, (unsigned int)SS);

    style_kernel<<<(BN*CO*CO + 255)/256, 256>>>(stg);

    hist_loss_kernel<<<NCS/2048, 256>>>();

    finalize_kernel<<<1, 32>>>(out);
    (void)in_sizes; (void)n_in; (void)out_size;
}

// round 13
// speedup vs baseline: 1.4230x; 1.0940x over previous
#include <cuda_runtime.h>
#include <cuda_bf16.h>

#define BN   4
#define CIN  3
#define CO   64
#define HH   512
#define WW   512
#define SS   (HH*WW)        /* 262144 = 2^18 */
#define NC   (BN*CO)        /* 256 */
#define HR   448
#define MM   (HR*HR)        /* 200704 */
#define NCS  (NC*SS)        /* 67108864 */
#define NCM  (NC*MM)        /* 51380224 */
#define KB   65536          /* bins per channel (16-bit sortable key) */

// ---------------- static device scratch (no runtime allocation) ----------------
__device__ unsigned int   g_hist_src_p[NC*KB/2];  // packed u16 counts (32 MB)
__device__ unsigned int   g_hist_ref_p[NC*KB/2];  // packed u16 counts (32 MB)
__device__ unsigned int   g_cdf_src[NC*KB];       // u32 exclusive CDF (64 MB)
__device__ unsigned int   g_cdf_ref[NC*KB];       // u32 exclusive CDF (64 MB)
__device__ unsigned int   g_zero[NC];             // oversized zero-bin counts
__device__ unsigned short g_src_sorted[NCS];      // 134 MB sorted src keys (u16)
__device__ unsigned short g_ref_sorted[NCM];      // 100 MB sorted ref keys (u16)
__device__ double         g_accum[3];             // content, style, hist sums
__device__ float          g_gram[BN*CO*CO];

// ---------------- helpers ----------------
__device__ __forceinline__ unsigned int f2s(float x) {
    unsigned int u = __float_as_uint(x);
    return (u & 0x80000000u) ? ~u : (u | 0x80000000u);
}
__device__ __forceinline__ float s2f(unsigned int k) {
    unsigned int u = (k & 0x80000000u) ? (k ^ 0x80000000u) : ~k;
    return __uint_as_float(u);
}
__device__ __forceinline__ float key2f(unsigned int k16) {
    return s2f((k16 << 16) | 0x8000u);
}

// packed f32x2 (FFMA2) helpers
__device__ __forceinline__ unsigned long long pk2(float lo, float hi) {
    unsigned long long r;
    asm("mov.b64 %0, {%1, %2};" : "=l"(r) : "f"(lo), "f"(hi));
    return r;
}
__device__ __forceinline__ void upk2(unsigned long long v, float& lo, float& hi) {
    asm("mov.b64 {%0, %1}, %2;" : "=f"(lo), "=f"(hi) : "l"(v));
}
__device__ __forceinline__ unsigned long long fma2(unsigned long long a,
                                                   unsigned long long b,
                                                   unsigned long long c) {
    unsigned long long d;
    asm("fma.rn.f32x2 %0, %1, %2, %3;" : "=l"(d) : "l"(a), "l"(b), "l"(c));
    return d;
}

__device__ __forceinline__ void block_add(double v, double* target) {
    __shared__ double sh[8];
    int tid  = threadIdx.x + threadIdx.y * blockDim.x;
    int lane = tid & 31, wid = tid >> 5;
    int nwarps = (blockDim.x * blockDim.y + 31) >> 5;
    #pragma unroll
    for (int o = 16; o > 0; o >>= 1) v += __shfl_down_sync(0xffffffffu, v, o);
    if (lane == 0) sh[wid] = v;
    __syncthreads();
    if (wid == 0) {
        v = (lane < nwarps) ? sh[lane] : 0.0;
        #pragma unroll
        for (int o = 4; o > 0; o >>= 1) v += __shfl_down_sync(0xffffffffu, v, o);
        if (lane == 0) atomicAdd(target, v);
    }
}

// ---------------- init ----------------
__global__ void init_kernel() {
    int i = blockIdx.x * 256 + threadIdx.x;
    if (i < 3) g_accum[i] = 0.0;
    if (i < BN*CO*CO) g_gram[i] = 0.0f;
}

// ------ conv + bias + relu + content-loss (fused; low register pressure) ------
__global__ void conv_kernel(const float* __restrict__ img, const float* __restrict__ w,
                            const float* __restrict__ b,   const float* __restrict__ ct,
                            float* __restrict__ out) {
    __shared__ float sin[3][10][34];
    __shared__ float sw[27][64];
    __shared__ float sb[64];
    const int n  = blockIdx.z;
    const int x0 = blockIdx.x * 32;
    const int y0 = blockIdx.y * 8;
    const int tid = threadIdx.y * 32 + threadIdx.x;

    for (int i = tid; i < 1728; i += 256) { int co = i / 27, tap = i % 27; sw[tap][co] = w[i]; }
    if (tid < 64) sb[tid] = b[tid];

    const float mean[3] = {0.485f, 0.456f, 0.406f};
    const float istd[3] = {1.f/0.229f, 1.f/0.224f, 1.f/0.225f};
    #pragma unroll
    for (int c = 0; c < 3; c++) {
        for (int i = tid; i < 340; i += 256) {
            int r = i / 34, cc = i % 34;
            int gy = y0 + r - 1, gx = x0 + cc - 1;
            float v = 0.f;
            if (gy >= 0 && gy < HH && gx >= 0 && gx < WW)
                v = (img[((n*3 + c)*HH + gy)*WW + gx] - mean[c]) * istd[c];
            sin[c][r][cc] = v;
        }
    }
    __syncthreads();

    const int px = threadIdx.x, py = threadIdx.y;
    float v[27];
    #pragma unroll
    for (int c = 0; c < 3; c++)
        #pragma unroll
        for (int ky = 0; ky < 3; ky++)
            #pragma unroll
            for (int kx = 0; kx < 3; kx++)
                v[c*9 + ky*3 + kx] = sin[c][py + ky][px + kx];

    const int y = y0 + py, x = x0 + px;
    float fsum = 0.f;
    #pragma unroll
    for (int cb = 0; cb < 64; cb += 16) {
        unsigned long long acc2[8];
        #pragma unroll
        for (int j = 0; j < 8; j++) acc2[j] = *(const unsigned long long*)&sb[cb + 2*j];
        #pragma unroll
        for (int t2 = 0; t2 < 27; t2++) {
            unsigned long long vv = pk2(v[t2], v[t2]);
            #pragma unroll
            for (int j = 0; j < 8; j++)
                acc2[j] = fma2(vv, *(const unsigned long long*)&sw[t2][cb + 2*j], acc2[j]);
        }
        #pragma unroll
        for (int j = 0; j < 8; j++) {
            float f0, f1;
            upk2(acc2[j], f0, f1);
            f0 = f0 > 0.f ? f0 : 0.f;
            f1 = f1 > 0.f ? f1 : 0.f;
            unsigned int ch0 = (unsigned int)(n*64 + cb + 2*j);
            unsigned int oi0 = ch0 * SS + (unsigned int)y * WW + x;
            out[oi0]      = f0;
            out[oi0 + SS] = f1;
            float d0 = f0 - ct[oi0];
            float d1 = f1 - ct[oi0 + SS];
            fsum = fmaf(d0, d0, fsum);
            fsum = fmaf(d1, d1, fsum);
        }
    }
    block_add((double)fsum, &g_accum[0]);
}

// ------ per-channel histogram of feat: plain smem atomics ------
__global__ void __launch_bounds__(1024) src_hist_kernel(const float4* __restrict__ feat) {
    extern __shared__ unsigned int sh[];  // KB/2 = 32768 words
    __shared__ unsigned int zwarp[32];
    const int ch  = blockIdx.x;
    const int tid = threadIdx.x;
    const int lane = tid & 31, wid = tid >> 5;
    for (int i = tid; i < KB/2; i += 1024) sh[i] = 0;
    __syncthreads();

    const float4* p = feat + (size_t)ch * (SS/4);
    unsigned int zc = 0;
    for (int i = tid; i < SS/4; i += 1024) {
        float4 v = p[i];
        float e[4] = {v.x, v.y, v.z, v.w};
        #pragma unroll
        for (int j = 0; j < 4; j++) {
            float f = e[j];
            if (f == 0.f) { zc++; }
            else {
                unsigned int k = f2s(f) >> 16;
                atomicAdd(&sh[k >> 1], 1u << ((k & 1) * 16));
            }
        }
    }
    #pragma unroll
    for (int o = 16; o > 0; o >>= 1) zc += __shfl_down_sync(0xffffffffu, zc, o);
    if (lane == 0) zwarp[wid] = zc;
    __syncthreads();
    if (tid == 0) {
        unsigned int s = 0;
        #pragma unroll
        for (int i = 0; i < 32; i++) s += zwarp[i];
        g_zero[ch] = s;
    }

    unsigned int* g = &g_hist_src_p[(size_t)ch * (KB/2)];
    for (int i = tid; i < KB/2; i += 1024) g[i] = sh[i];
}

// ------ per-channel histogram of ref target ------
__global__ void __launch_bounds__(1024) ref_hist_kernel(const float4* __restrict__ vals) {
    extern __shared__ unsigned int sh[];
    const int ch  = blockIdx.x;
    const int tid = threadIdx.x;
    for (int i = tid; i < KB/2; i += 1024) sh[i] = 0;
    __syncthreads();

    const float4* p = vals + (size_t)ch * (MM/4);
    for (int i = tid; i < MM/4; i += 1024) {
        float4 v = p[i];
        float e[4] = {v.x, v.y, v.z, v.w};
        #pragma unroll
        for (int j = 0; j < 4; j++) {
            unsigned int k = f2s(e[j]) >> 16;
            atomicAdd(&sh[k >> 1], 1u << ((k & 1) * 16));
        }
    }
    __syncthreads();

    unsigned int* g = &g_hist_ref_p[(size_t)ch * (KB/2)];
    for (int i = tid; i < KB/2; i += 1024) g[i] = sh[i];
}

// ------ per-channel exclusive scan: packed u16 hist -> u32 CDF ------
__global__ void scan_kernel(const unsigned int* __restrict__ packed,
                            unsigned int* __restrict__ cdf,
                            const unsigned int* __restrict__ zero) {
    const int ch = blockIdx.x;
    const unsigned int* hp = packed + (size_t)ch * (KB/2);
    unsigned int* cp = cdf + (size_t)ch * KB;
    const int tid = threadIdx.x;         // 1024 threads
    const int lane = tid & 31, wid = tid >> 5;
    __shared__ unsigned int wsum[32];
    __shared__ unsigned int btot;
    unsigned int carry = 0;
    #pragma unroll
    for (int tile = 0; tile < 4; tile++) {
        const int wbase = tile * 8192 + tid * 8;
        uint4 a0 = *(const uint4*)&hp[wbase + 0];
        uint4 a1 = *(const uint4*)&hp[wbase + 4];
        unsigned int wv[8] = {a0.x,a0.y,a0.z,a0.w, a1.x,a1.y,a1.z,a1.w};
        unsigned int e[16];
        #pragma unroll
        for (int i = 0; i < 8; i++) { e[2*i] = wv[i] & 0xffffu; e[2*i+1] = wv[i] >> 16; }
        if (zero && tile == 2 && tid == 0) e[0] += zero[ch];  // bin 32768
        unsigned int tsum = 0;
        #pragma unroll
        for (int i = 0; i < 16; i++) tsum += e[i];
        unsigned int inc = tsum;
        #pragma unroll
        for (int o = 1; o < 32; o <<= 1) {
            unsigned int nv = __shfl_up_sync(0xffffffffu, inc, o);
            if (lane >= o) inc += nv;
        }
        if (lane == 31) wsum[wid] = inc;
        __syncthreads();
        if (wid == 0) {
            unsigned int v0 = wsum[lane];
            unsigned int inc2 = v0;
            #pragma unroll
            for (int o = 1; o < 32; o <<= 1) {
                unsigned int nv = __shfl_up_sync(0xffffffffu, inc2, o);
                if (lane >= o) inc2 += nv;
            }
            wsum[lane] = inc2 - v0;
            if (lane == 31) btot = inc2;
        }
        __syncthreads();
        unsigned int run = carry + wsum[wid] + (inc - tsum);
        unsigned int o_[16];
        #pragma unroll
        for (int i = 0; i < 16; i++) { o_[i] = run; run += e[i]; }
        const int obase = tile * 16384 + tid * 16;
        *(uint4*)&cp[obase + 0]  = make_uint4(o_[0], o_[1], o_[2], o_[3]);
        *(uint4*)&cp[obase + 4]  = make_uint4(o_[4], o_[5], o_[6], o_[7]);
        *(uint4*)&cp[obase + 8]  = make_uint4(o_[8], o_[9], o_[10], o_[11]);
        *(uint4*)&cp[obase + 12] = make_uint4(o_[12], o_[13], o_[14], o_[15]);
        carry += btot;
        __syncthreads();
    }
}

// ------- counting-sort writeout of u16 keys (store-only: imbalance-benign) -------
__global__ void writeout_kernel(const unsigned int* __restrict__ cdf,
                                unsigned short* __restrict__ sorted, unsigned int seglen) {
    const int ch  = blockIdx.y;
    const int lane = threadIdx.x & 31, wid = threadIdx.x >> 5;
    const int b0 = blockIdx.x * 256 + wid * 32;
    const unsigned int* __restrict__ cum = cdf + (size_t)ch * KB;
    unsigned short* __restrict__ outp = sorted + (size_t)ch * seglen;
    const int b = b0 + lane;
    unsigned int p0v = cum[b];
    unsigned int p1v = (b == KB - 1) ? seglen : cum[b + 1];
    for (int k = 0; k < 32; k++) {
        unsigned int p0 = __shfl_sync(0xffffffffu, p0v, k);
        unsigned int p1 = __shfl_sync(0xffffffffu, p1v, k);
        if (p1 > p0) {
            unsigned short kv = (unsigned short)(b0 + k);
            for (unsigned int p = p0 + lane; p < p1; p += 32) outp[p] = kv;
        }
    }
}

// ------- hist loss: position-parallel streaming over u16 keys -------
__global__ void hist_loss_kernel() {
    const unsigned int t = blockIdx.x * 256u + threadIdx.x;   // 8 keys per thread
    const unsigned int base = t * 8u;
    const unsigned int c = base >> 18;          // / SS
    const unsigned int i = base & (SS - 1);
    const float step = (float)(MM - 1) / (float)(SS - 1);
    uint4 kv = *(const uint4*)&g_src_sorted[base];
    const unsigned short* __restrict__ refq = &g_ref_sorted[(size_t)c * MM];
    unsigned int kw[4] = {kv.x, kv.y, kv.z, kv.w};
    float fsum = 0.f;
    #pragma unroll
    for (int j = 0; j < 8; j++) {
        unsigned int k16 = (kw[j >> 1] >> ((j & 1) * 16)) & 0xffffu;
        float v = key2f(k16);
        float pos = step * (float)(i + j);
        int lo = (int)pos;
        float w = pos - (float)lo;
        int hi = lo + (w > 0.f ? 1 : 0);
        if (hi > MM - 1) hi = MM - 1;
        float rlo = key2f((unsigned int)refq[lo]);
        float rhi = key2f((unsigned int)refq[hi]);
        float r = rlo * (1.0f - w) + rhi * w;
        float d = v - r;
        fsum = fmaf(d, d, fsum);
    }
    block_add((double)fsum, &g_accum[2]);
}

// ------ gram: per-batch F F^T, smem-tiled, FFMA2, forced 4 blocks/SM ------
#define GK 1024
#define GC 128
__global__ void __launch_bounds__(256, 4) gram_kernel(const float* __restrict__ feat) {
    __shared__ float tile[GC][68];
    const int n = blockIdx.y;
    const int base = blockIdx.x * GK;
    const int tid = threadIdx.x;
    const int r0 = (tid / 16) * 4, c0 = (tid % 16) * 4;
    unsigned long long acc01[4] = {0,0,0,0};
    unsigned long long acc23[4] = {0,0,0,0};
    for (int cb = 0; cb < GK; cb += GC) {
        __syncthreads();
        #pragma unroll
        for (int it = 0; it < 32; it++) {
            int li = it * 256 + tid;
            int ch = li >> 7, k = li & 127;
            tile[k][ch] = feat[(unsigned int)(n*64 + ch) * SS + base + cb + k];
        }
        __syncthreads();
        #pragma unroll 4
        for (int k = 0; k < GC; k++) {
            float4 a = *(const float4*)&tile[k][r0];
            float4 bq = *(const float4*)&tile[k][c0];
            unsigned long long b01, b23;
            b01 = pk2(bq.x, bq.y);
            b23 = pk2(bq.z, bq.w);
            float ae[4] = {a.x, a.y, a.z, a.w};
            #pragma unroll
            for (int i = 0; i < 4; i++) {
                unsigned long long aa = pk2(ae[i], ae[i]);
                acc01[i] = fma2(aa, b01, acc01[i]);
                acc23[i] = fma2(aa, b23, acc23[i]);
            }
        }
    }
    #pragma unroll
    for (int i = 0; i < 4; i++) {
        float f0, f1, f2, f3;
        upk2(acc01[i], f0, f1);
        upk2(acc23[i], f2, f3);
        float* gg = &g_gram[n*4096 + (r0 + i)*64 + c0];
        atomicAdd(&gg[0], f0);
        atomicAdd(&gg[1], f1);
        atomicAdd(&gg[2], f2);
        atomicAdd(&gg[3], f3);
    }
}

// ---------------- style loss ----------------
__global__ void style_kernel(const float* __restrict__ tgt) {
    int i = blockIdx.x * 256 + threadIdx.x;
    double d = 0.0;
    if (i < BN*CO*CO) {
        float g = g_gram[i] * (1.0f / ((float)CO * HH * WW));
        float df = g - tgt[i];
        d = (double)df * (double)df;
    }
    block_add(d, &g_accum[1]);
}

// ---------------- finalize ----------------
__global__ void finalize_kernel(float* __restrict__ out) {
    if (threadIdx.x == 0) {
        out[NCS + 0] = (float)(g_accum[0] / (double)NCS);
        out[NCS + 1] = (float)(g_accum[1] / (double)(BN*CO*CO));
        out[NCS + 2] = (float)(g_accum[2] / (double)NCS);
    }
}

// ---------------- launch: fork/join streams for chain overlap ----------------
extern "C" void kernel_launch(void* const* d_in, const int* in_sizes, int n_in,
                              void* d_out, int out_size) {
    const float* img  = (const float*)d_in[0];
    const float* w    = (const float*)d_in[1];
    const float* b    = (const float*)d_in[2];
    const float* ct   = (const float*)d_in[3];
    const float* stg  = (const float*)d_in[4];
    const float* hist = (const float*)d_in[5];
    float* out = (float*)d_out;

    void *p_hsp, *p_hrp, *p_cs, *p_cr, *p_z, *p_ss, *p_rs;
    cudaGetSymbolAddress(&p_hsp, g_hist_src_p);
    cudaGetSymbolAddress(&p_hrp, g_hist_ref_p);
    cudaGetSymbolAddress(&p_cs,  g_cdf_src);
    cudaGetSymbolAddress(&p_cr,  g_cdf_ref);
    cudaGetSymbolAddress(&p_z,   g_zero);
    cudaGetSymbolAddress(&p_ss,  g_src_sorted);
    cudaGetSymbolAddress(&p_rs,  g_ref_sorted);

    static cudaStream_t sB = 0, sC = 0;
    static cudaEvent_t eInit = 0, eConv = 0, eRef = 0, eC = 0;
    if (!sB) {
        cudaStreamCreateWithFlags(&sB, cudaStreamNonBlocking);
        cudaStreamCreateWithFlags(&sC, cudaStreamNonBlocking);
        cudaEventCreateWithFlags(&eInit, cudaEventDisableTiming);
        cudaEventCreateWithFlags(&eConv, cudaEventDisableTiming);
        cudaEventCreateWithFlags(&eRef,  cudaEventDisableTiming);
        cudaEventCreateWithFlags(&eC,    cudaEventDisableTiming);
        cudaFuncSetAttribute(src_hist_kernel, cudaFuncAttributeMaxDynamicSharedMemorySize, 131072);
        cudaFuncSetAttribute(ref_hist_kernel, cudaFuncAttributeMaxDynamicSharedMemorySize, 131072);
    }

    // stream 0: init, then fork
    init_kernel<<<64, 256>>>();
    cudaEventRecord(eInit, 0);

    // chain B (sB): ref-target pipeline — independent of conv
    cudaStreamWaitEvent(sB, eInit, 0);
    ref_hist_kernel<<<NC, 1024, 131072, sB>>>((const float4*)hist);
    scan_kernel<<<NC, 1024, 0, sB>>>((const unsigned int*)p_hrp, (unsigned int*)p_cr,
                                     (const unsigned int*)0);
    writeout_kernel<<<dim3(KB/256, NC), 256, 0, sB>>>((const unsigned int*)p_cr,
                                                      (unsigned short*)p_rs, (unsigned int)MM);
    cudaEventRecord(eRef, sB);

    // stream 0: conv
    dim3 cgrid(WW/32, HH/8, BN), cblk(32, 8);
    conv_kernel<<<cgrid, cblk>>>(img, w, b, ct, out);
    cudaEventRecord(eConv, 0);

    // chain C (sC): gram + style — only needs conv output
    cudaStreamWaitEvent(sC, eConv, 0);
    gram_kernel<<<dim3(SS/GK, BN), 256, 0, sC>>>(out);
    style_kernel<<<(BN*CO*CO + 255)/256, 256, 0, sC>>>(stg);
    cudaEventRecord(eC, sC);

    // stream 0: src histogram pipeline (overlaps with gram + ref chain)
    src_hist_kernel<<<NC, 1024, 131072>>>((const float4*)out);
    scan_kernel<<<NC, 1024>>>((const unsigned int*)p_hsp, (unsigned int*)p_cs,
                              (const unsigned int*)p_z);
    writeout_kernel<<<dim3(KB/256, NC), 256>>>((const unsigned int*)p_cs,
                                               (unsigned short*)p_ss, (unsigned int)SS);

    // join: hist_loss needs both sorted arrays
    cudaStreamWaitEvent(0, eRef, 0);
    hist_loss_kernel<<<NCS/2048, 256>>>();

    // join: finalize needs style (chain C) + everything on stream 0
    cudaStreamWaitEvent(0, eC, 0);
    finalize_kernel<<<1, 32>>>(out);

    (void)in_sizes; (void)n_in; (void)out_size;
}

// round 14
// speedup vs baseline: 1.8661x; 1.3113x over previous
#include <cuda_runtime.h>
#include <cuda_bf16.h>

#define BN   4
#define CIN  3
#define CO   64
#define HH   512
#define WW   512
#define SS   (HH*WW)        /* 262144 = 2^18 */
#define NC   (BN*CO)        /* 256 */
#define HR   448
#define MM   (HR*HR)        /* 200704 */
#define NCS  (NC*SS)        /* 67108864 */
#define NCM  (NC*MM)        /* 51380224 */
#define KB   65536          /* bins per channel (16-bit sortable key) */

// ---------------- static device scratch (no runtime allocation) ----------------
__device__ unsigned int   g_hist_src_p[NC*KB/2];  // packed u16 counts (32 MB)
__device__ unsigned int   g_hist_ref_p[NC*KB/2];  // packed u16 counts (32 MB)
__device__ unsigned int   g_cdf_src[NC*KB];       // u32 exclusive CDF (64 MB)
__device__ unsigned int   g_cdf_ref[NC*KB];       // u32 exclusive CDF (64 MB)
__device__ unsigned int   g_zero[NC];             // oversized zero-bin counts
__device__ unsigned short g_src_sorted[NCS];      // 134 MB sorted src keys (u16)
__device__ unsigned short g_ref_sorted[NCM];      // 100 MB sorted ref keys (u16)
__device__ double         g_accum[3];             // content, style, hist sums
__device__ float          g_gram[BN*CO*CO];

// ---------------- helpers ----------------
__device__ __forceinline__ unsigned int f2s(float x) {
    unsigned int u = __float_as_uint(x);
    return (u & 0x80000000u) ? ~u : (u | 0x80000000u);
}
__device__ __forceinline__ float s2f(unsigned int k) {
    unsigned int u = (k & 0x80000000u) ? (k ^ 0x80000000u) : ~k;
    return __uint_as_float(u);
}
__device__ __forceinline__ float key2f(unsigned int k16) {
    return s2f((k16 << 16) | 0x8000u);
}

// packed f32x2 (FFMA2) helpers
__device__ __forceinline__ unsigned long long pk2(float lo, float hi) {
    unsigned long long r;
    asm("mov.b64 %0, {%1, %2};" : "=l"(r) : "f"(lo), "f"(hi));
    return r;
}
__device__ __forceinline__ void upk2(unsigned long long v, float& lo, float& hi) {
    asm("mov.b64 {%0, %1}, %2;" : "=f"(lo), "=f"(hi) : "l"(v));
}
__device__ __forceinline__ unsigned long long fma2(unsigned long long a,
                                                   unsigned long long b,
                                                   unsigned long long c) {
    unsigned long long d;
    asm("fma.rn.f32x2 %0, %1, %2, %3;" : "=l"(d) : "l"(a), "l"(b), "l"(c));
    return d;
}

__device__ __forceinline__ void block_add(double v, double* target) {
    __shared__ double sh[8];
    int tid  = threadIdx.x + threadIdx.y * blockDim.x;
    int lane = tid & 31, wid = tid >> 5;
    int nwarps = (blockDim.x * blockDim.y + 31) >> 5;
    #pragma unroll
    for (int o = 16; o > 0; o >>= 1) v += __shfl_down_sync(0xffffffffu, v, o);
    if (lane == 0) sh[wid] = v;
    __syncthreads();
    if (wid == 0) {
        v = (lane < nwarps) ? sh[lane] : 0.0;
        #pragma unroll
        for (int o = 4; o > 0; o >>= 1) v += __shfl_down_sync(0xffffffffu, v, o);
        if (lane == 0) atomicAdd(target, v);
    }
}

// ---------------- init ----------------
__global__ void init_kernel() {
    int i = blockIdx.x * 256 + threadIdx.x;
    if (i < 3) g_accum[i] = 0.0;
    if (i < BN*CO*CO) g_gram[i] = 0.0f;
}

// ------ conv + bias + relu + content-loss (fused; low register pressure) ------
__global__ void conv_kernel(const float* __restrict__ img, const float* __restrict__ w,
                            const float* __restrict__ b,   const float* __restrict__ ct,
                            float* __restrict__ out) {
    __shared__ float sin[3][10][34];
    __shared__ float sw[27][64];
    __shared__ float sb[64];
    const int n  = blockIdx.z;
    const int x0 = blockIdx.x * 32;
    const int y0 = blockIdx.y * 8;
    const int tid = threadIdx.y * 32 + threadIdx.x;

    for (int i = tid; i < 1728; i += 256) { int co = i / 27, tap = i % 27; sw[tap][co] = w[i]; }
    if (tid < 64) sb[tid] = b[tid];

    const float mean[3] = {0.485f, 0.456f, 0.406f};
    const float istd[3] = {1.f/0.229f, 1.f/0.224f, 1.f/0.225f};
    #pragma unroll
    for (int c = 0; c < 3; c++) {
        for (int i = tid; i < 340; i += 256) {
            int r = i / 34, cc = i % 34;
            int gy = y0 + r - 1, gx = x0 + cc - 1;
            float v = 0.f;
            if (gy >= 0 && gy < HH && gx >= 0 && gx < WW)
                v = (img[((n*3 + c)*HH + gy)*WW + gx] - mean[c]) * istd[c];
            sin[c][r][cc] = v;
        }
    }
    __syncthreads();

    const int px = threadIdx.x, py = threadIdx.y;
    float v[27];
    #pragma unroll
    for (int c = 0; c < 3; c++)
        #pragma unroll
        for (int ky = 0; ky < 3; ky++)
            #pragma unroll
            for (int kx = 0; kx < 3; kx++)
                v[c*9 + ky*3 + kx] = sin[c][py + ky][px + kx];

    const int y = y0 + py, x = x0 + px;
    float fsum = 0.f;
    #pragma unroll
    for (int cb = 0; cb < 64; cb += 16) {
        unsigned long long acc2[8];
        #pragma unroll
        for (int j = 0; j < 8; j++) acc2[j] = *(const unsigned long long*)&sb[cb + 2*j];
        #pragma unroll
        for (int t2 = 0; t2 < 27; t2++) {
            unsigned long long vv = pk2(v[t2], v[t2]);
            #pragma unroll
            for (int j = 0; j < 8; j++)
                acc2[j] = fma2(vv, *(const unsigned long long*)&sw[t2][cb + 2*j], acc2[j]);
        }
        #pragma unroll
        for (int j = 0; j < 8; j++) {
            float f0, f1;
            upk2(acc2[j], f0, f1);
            f0 = f0 > 0.f ? f0 : 0.f;
            f1 = f1 > 0.f ? f1 : 0.f;
            unsigned int ch0 = (unsigned int)(n*64 + cb + 2*j);
            unsigned int oi0 = ch0 * SS + (unsigned int)y * WW + x;
            out[oi0]      = f0;
            out[oi0 + SS] = f1;
            float d0 = f0 - ct[oi0];
            float d1 = f1 - ct[oi0 + SS];
            fsum = fmaf(d0, d0, fsum);
            fsum = fmaf(d1, d1, fsum);
        }
    }
    block_add((double)fsum, &g_accum[0]);
}

// ------ per-channel histogram of feat: plain smem atomics ------
__global__ void __launch_bounds__(1024) src_hist_kernel(const float4* __restrict__ feat) {
    extern __shared__ unsigned int sh[];  // KB/2 = 32768 words
    __shared__ unsigned int zwarp[32];
    const int ch  = blockIdx.x;
    const int tid = threadIdx.x;
    const int lane = tid & 31, wid = tid >> 5;
    for (int i = tid; i < KB/2; i += 1024) sh[i] = 0;
    __syncthreads();

    const float4* p = feat + (size_t)ch * (SS/4);
    unsigned int zc = 0;
    for (int i = tid; i < SS/4; i += 1024) {
        float4 v = p[i];
        float e[4] = {v.x, v.y, v.z, v.w};
        #pragma unroll
        for (int j = 0; j < 4; j++) {
            float f = e[j];
            if (f == 0.f) { zc++; }
            else {
                unsigned int k = f2s(f) >> 16;
                atomicAdd(&sh[k >> 1], 1u << ((k & 1) * 16));
            }
        }
    }
    #pragma unroll
    for (int o = 16; o > 0; o >>= 1) zc += __shfl_down_sync(0xffffffffu, zc, o);
    if (lane == 0) zwarp[wid] = zc;
    __syncthreads();
    if (tid == 0) {
        unsigned int s = 0;
        #pragma unroll
        for (int i = 0; i < 32; i++) s += zwarp[i];
        g_zero[ch] = s;
    }

    unsigned int* g = &g_hist_src_p[(size_t)ch * (KB/2)];
    for (int i = tid; i < KB/2; i += 1024) g[i] = sh[i];
}

// ------ per-channel histogram of ref target ------
__global__ void __launch_bounds__(1024) ref_hist_kernel(const float4* __restrict__ vals) {
    extern __shared__ unsigned int sh[];
    const int ch  = blockIdx.x;
    const int tid = threadIdx.x;
    for (int i = tid; i < KB/2; i += 1024) sh[i] = 0;
    __syncthreads();

    const float4* p = vals + (size_t)ch * (MM/4);
    for (int i = tid; i < MM/4; i += 1024) {
        float4 v = p[i];
        float e[4] = {v.x, v.y, v.z, v.w};
        #pragma unroll
        for (int j = 0; j < 4; j++) {
            unsigned int k = f2s(e[j]) >> 16;
            atomicAdd(&sh[k >> 1], 1u << ((k & 1) * 16));
        }
    }
    __syncthreads();

    unsigned int* g = &g_hist_ref_p[(size_t)ch * (KB/2)];
    for (int i = tid; i < KB/2; i += 1024) g[i] = sh[i];
}

// ------ per-channel exclusive scan: packed u16 hist -> u32 CDF ------
__global__ void scan_kernel(const unsigned int* __restrict__ packed,
                            unsigned int* __restrict__ cdf,
                            const unsigned int* __restrict__ zero) {
    const int ch = blockIdx.x;
    const unsigned int* hp = packed + (size_t)ch * (KB/2);
    unsigned int* cp = cdf + (size_t)ch * KB;
    const int tid = threadIdx.x;         // 1024 threads
    const int lane = tid & 31, wid = tid >> 5;
    __shared__ unsigned int wsum[32];
    __shared__ unsigned int btot;
    unsigned int carry = 0;
    #pragma unroll
    for (int tile = 0; tile < 4; tile++) {
        const int wbase = tile * 8192 + tid * 8;
        uint4 a0 = *(const uint4*)&hp[wbase + 0];
        uint4 a1 = *(const uint4*)&hp[wbase + 4];
        unsigned int wv[8] = {a0.x,a0.y,a0.z,a0.w, a1.x,a1.y,a1.z,a1.w};
        unsigned int e[16];
        #pragma unroll
        for (int i = 0; i < 8; i++) { e[2*i] = wv[i] & 0xffffu; e[2*i+1] = wv[i] >> 16; }
        if (zero && tile == 2 && tid == 0) e[0] += zero[ch];  // bin 32768
        unsigned int tsum = 0;
        #pragma unroll
        for (int i = 0; i < 16; i++) tsum += e[i];
        unsigned int inc = tsum;
        #pragma unroll
        for (int o = 1; o < 32; o <<= 1) {
            unsigned int nv = __shfl_up_sync(0xffffffffu, inc, o);
            if (lane >= o) inc += nv;
        }
        if (lane == 31) wsum[wid] = inc;
        __syncthreads();
        if (wid == 0) {
            unsigned int v0 = wsum[lane];
            unsigned int inc2 = v0;
            #pragma unroll
            for (int o = 1; o < 32; o <<= 1) {
                unsigned int nv = __shfl_up_sync(0xffffffffu, inc2, o);
                if (lane >= o) inc2 += nv;
            }
            wsum[lane] = inc2 - v0;
            if (lane == 31) btot = inc2;
        }
        __syncthreads();
        unsigned int run = carry + wsum[wid] + (inc - tsum);
        unsigned int o_[16];
        #pragma unroll
        for (int i = 0; i < 16; i++) { o_[i] = run; run += e[i]; }
        const int obase = tile * 16384 + tid * 16;
        *(uint4*)&cp[obase + 0]  = make_uint4(o_[0], o_[1], o_[2], o_[3]);
        *(uint4*)&cp[obase + 4]  = make_uint4(o_[4], o_[5], o_[6], o_[7]);
        *(uint4*)&cp[obase + 8]  = make_uint4(o_[8], o_[9], o_[10], o_[11]);
        *(uint4*)&cp[obase + 12] = make_uint4(o_[12], o_[13], o_[14], o_[15]);
        carry += btot;
        __syncthreads();
    }
}

// ------- counting-sort writeout: ballot-skip empty bins + uint4 vector fill -------
__global__ void writeout_kernel(const unsigned int* __restrict__ cdf,
                                unsigned short* __restrict__ sorted, unsigned int seglen) {
    const int ch  = blockIdx.y;
    const int lane = threadIdx.x & 31, wid = threadIdx.x >> 5;
    const int b0 = blockIdx.x * 256 + wid * 32;
    const unsigned int* __restrict__ cum = cdf + (size_t)ch * KB;
    unsigned short* __restrict__ outp = sorted + (size_t)ch * seglen;
    const int b = b0 + lane;
    unsigned int p0 = cum[b];
    unsigned int p1 = (b == KB - 1) ? seglen : cum[b + 1];
    unsigned int mask = __ballot_sync(0xffffffffu, p1 > p0);
    while (mask) {
        int k = __ffs(mask) - 1;
        mask &= mask - 1;
        unsigned int q0 = __shfl_sync(0xffffffffu, p0, k);
        unsigned int q1 = __shfl_sync(0xffffffffu, p1, k);
        unsigned short kv = (unsigned short)(b0 + k);
        unsigned int a0 = (q0 + 7u) & ~7u;      // 8-elem (16B) aligned interior
        unsigned int a1 = q1 & ~7u;
        if (a1 > a0) {
            if (q0 + lane < a0) outp[q0 + lane] = kv;          // head (<8)
            unsigned int kk = ((unsigned int)kv << 16) | kv;
            uint4 vv = make_uint4(kk, kk, kk, kk);
            for (unsigned int p = a0 + (unsigned int)lane * 8u; p < a1; p += 256u)
                *(uint4*)&outp[p] = vv;
            if (a1 + lane < q1) outp[a1 + lane] = kv;          // tail (<8)
        } else {
            if (q0 + lane < q1) outp[q0 + lane] = kv;          // short run (<15)
        }
    }
}

// ------- hist loss: position-parallel streaming over u16 keys -------
__global__ void hist_loss_kernel() {
    const unsigned int t = blockIdx.x * 256u + threadIdx.x;   // 8 keys per thread
    const unsigned int base = t * 8u;
    const unsigned int c = base >> 18;          // / SS
    const unsigned int i = base & (SS - 1);
    const float step = (float)(MM - 1) / (float)(SS - 1);
    uint4 kv = *(const uint4*)&g_src_sorted[base];
    const unsigned short* __restrict__ refq = &g_ref_sorted[(size_t)c * MM];
    unsigned int kw[4] = {kv.x, kv.y, kv.z, kv.w};
    float fsum = 0.f;
    #pragma unroll
    for (int j = 0; j < 8; j++) {
        unsigned int k16 = (kw[j >> 1] >> ((j & 1) * 16)) & 0xffffu;
        float v = key2f(k16);
        float pos = step * (float)(i + j);
        int lo = (int)pos;
        float w = pos - (float)lo;
        int hi = lo + (w > 0.f ? 1 : 0);
        if (hi > MM - 1) hi = MM - 1;
        float rlo = key2f((unsigned int)refq[lo]);
        float rhi = key2f((unsigned int)refq[hi]);
        float r = rlo * (1.0f - w) + rhi * w;
        float d = v - r;
        fsum = fmaf(d, d, fsum);
    }
    block_add((double)fsum, &g_accum[2]);
}

// ------ gram: per-batch F F^T, smem-tiled, FFMA2, forced 4 blocks/SM ------
#define GK 1024
#define GC 128
__global__ void __launch_bounds__(256, 4) gram_kernel(const float* __restrict__ feat) {
    __shared__ float tile[GC][68];
    const int n = blockIdx.y;
    const int base = blockIdx.x * GK;
    const int tid = threadIdx.x;
    const int r0 = (tid / 16) * 4, c0 = (tid % 16) * 4;
    unsigned long long acc01[4] = {0,0,0,0};
    unsigned long long acc23[4] = {0,0,0,0};
    for (int cb = 0; cb < GK; cb += GC) {
        __syncthreads();
        #pragma unroll
        for (int it = 0; it < 32; it++) {
            int li = it * 256 + tid;
            int ch = li >> 7, k = li & 127;
            tile[k][ch] = feat[(unsigned int)(n*64 + ch) * SS + base + cb + k];
        }
        __syncthreads();
        #pragma unroll 4
        for (int k = 0; k < GC; k++) {
            float4 a = *(const float4*)&tile[k][r0];
            float4 bq = *(const float4*)&tile[k][c0];
            unsigned long long b01, b23;
            b01 = pk2(bq.x, bq.y);
            b23 = pk2(bq.z, bq.w);
            float ae[4] = {a.x, a.y, a.z, a.w};
            #pragma unroll
            for (int i = 0; i < 4; i++) {
                unsigned long long aa = pk2(ae[i], ae[i]);
                acc01[i] = fma2(aa, b01, acc01[i]);
                acc23[i] = fma2(aa, b23, acc23[i]);
            }
        }
    }
    #pragma unroll
    for (int i = 0; i < 4; i++) {
        float f0, f1, f2, f3;
        upk2(acc01[i], f0, f1);
        upk2(acc23[i], f2, f3);
        float* gg = &g_gram[n*4096 + (r0 + i)*64 + c0];
        atomicAdd(&gg[0], f0);
        atomicAdd(&gg[1], f1);
        atomicAdd(&gg[2], f2);
        atomicAdd(&gg[3], f3);
    }
}

// ---------------- style loss ----------------
__global__ void style_kernel(const float* __restrict__ tgt) {
    int i = blockIdx.x * 256 + threadIdx.x;
    double d = 0.0;
    if (i < BN*CO*CO) {
        float g = g_gram[i] * (1.0f / ((float)CO * HH * WW));
        float df = g - tgt[i];
        d = (double)df * (double)df;
    }
    block_add(d, &g_accum[1]);
}

// ---------------- finalize ----------------
__global__ void finalize_kernel(float* __restrict__ out) {
    if (threadIdx.x == 0) {
        out[NCS + 0] = (float)(g_accum[0] / (double)NCS);
        out[NCS + 1] = (float)(g_accum[1] / (double)(BN*CO*CO));
        out[NCS + 2] = (float)(g_accum[2] / (double)NCS);
    }
}

// ---------------- launch: fork/join streams for chain overlap ----------------
extern "C" void kernel_launch(void* const* d_in, const int* in_sizes, int n_in,
                              void* d_out, int out_size) {
    const float* img  = (const float*)d_in[0];
    const float* w    = (const float*)d_in[1];
    const float* b    = (const float*)d_in[2];
    const float* ct   = (const float*)d_in[3];
    const float* stg  = (const float*)d_in[4];
    const float* hist = (const float*)d_in[5];
    float* out = (float*)d_out;

    void *p_hsp, *p_hrp, *p_cs, *p_cr, *p_z, *p_ss, *p_rs;
    cudaGetSymbolAddress(&p_hsp, g_hist_src_p);
    cudaGetSymbolAddress(&p_hrp, g_hist_ref_p);
    cudaGetSymbolAddress(&p_cs,  g_cdf_src);
    cudaGetSymbolAddress(&p_cr,  g_cdf_ref);
    cudaGetSymbolAddress(&p_z,   g_zero);
    cudaGetSymbolAddress(&p_ss,  g_src_sorted);
    cudaGetSymbolAddress(&p_rs,  g_ref_sorted);

    static cudaStream_t sB = 0, sC = 0;
    static cudaEvent_t eInit = 0, eConv = 0, eRef = 0, eC = 0;
    if (!sB) {
        cudaStreamCreateWithFlags(&sB, cudaStreamNonBlocking);
        cudaStreamCreateWithFlags(&sC, cudaStreamNonBlocking);
        cudaEventCreateWithFlags(&eInit, cudaEventDisableTiming);
        cudaEventCreateWithFlags(&eConv, cudaEventDisableTiming);
        cudaEventCreateWithFlags(&eRef,  cudaEventDisableTiming);
        cudaEventCreateWithFlags(&eC,    cudaEventDisableTiming);
        cudaFuncSetAttribute(src_hist_kernel, cudaFuncAttributeMaxDynamicSharedMemorySize, 131072);
        cudaFuncSetAttribute(ref_hist_kernel, cudaFuncAttributeMaxDynamicSharedMemorySize, 131072);
    }

    // stream 0: init, then fork
    init_kernel<<<64, 256>>>();
    cudaEventRecord(eInit, 0);

    // chain B (sB): ref-target pipeline — independent of conv
    cudaStreamWaitEvent(sB, eInit, 0);
    ref_hist_kernel<<<NC, 1024, 131072, sB>>>((const float4*)hist);
    scan_kernel<<<NC, 1024, 0, sB>>>((const unsigned int*)p_hrp, (unsigned int*)p_cr,
                                     (const unsigned int*)0);
    writeout_kernel<<<dim3(KB/256, NC), 256, 0, sB>>>((const unsigned int*)p_cr,
                                                      (unsigned short*)p_rs, (unsigned int)MM);
    cudaEventRecord(eRef, sB);

    // stream 0: conv
    dim3 cgrid(WW/32, HH/8, BN), cblk(32, 8);
    conv_kernel<<<cgrid, cblk>>>(img, w, b, ct, out);
    cudaEventRecord(eConv, 0);

    // chain C (sC): gram + style — only needs conv output
    cudaStreamWaitEvent(sC, eConv, 0);
    gram_kernel<<<dim3(SS/GK, BN), 256, 0, sC>>>(out);
    style_kernel<<<(BN*CO*CO + 255)/256, 256, 0, sC>>>(stg);
    cudaEventRecord(eC, sC);

    // stream 0: src histogram pipeline (overlaps with gram + ref chain)
    src_hist_kernel<<<NC, 1024, 131072>>>((const float4*)out);
    scan_kernel<<<NC, 1024>>>((const unsigned int*)p_hsp, (unsigned int*)p_cs,
                              (const unsigned int*)p_z);
    writeout_kernel<<<dim3(KB/256, NC), 256>>>((const unsigned int*)p_cs,
                                               (unsigned short*)p_ss, (unsigned int)SS);

    // join: hist_loss needs both sorted arrays
    cudaStreamWaitEvent(0, eRef, 0);
    hist_loss_kernel<<<NCS/2048, 256>>>();

    // join: finalize needs style (chain C) + everything on stream 0
    cudaStreamWaitEvent(0, eC, 0);
    finalize_kernel<<<1, 32>>>(out);

    (void)in_sizes; (void)n_in; (void)out_size;
}

// round 16
// speedup vs baseline: 2.3086x; 1.2371x over previous
#include <cuda_runtime.h>
#include <cuda_bf16.h>

#define BN   4
#define CIN  3
#define CO   64
#define HH   512
#define WW   512
#define SS   (HH*WW)        /* 262144 = 2^18 */
#define NC   (BN*CO)        /* 256 */
#define HR   448
#define MM   (HR*HR)        /* 200704 */
#define NCS  (NC*SS)        /* 67108864 */
#define NCM  (NC*MM)        /* 51380224 */
#define KB   65536          /* bins per channel (16-bit sortable key) */

// ---------------- static device scratch (no runtime allocation) ----------------
__device__ unsigned int   g_hist_src_p[NC*KB/2];
__device__ unsigned int   g_hist_ref_p[NC*KB/2];
__device__ unsigned int   g_cdf_src[NC*KB];
__device__ unsigned int   g_cdf_ref[NC*KB];
__device__ unsigned int   g_zero[NC];
__device__ unsigned short g_src_sorted[NCS];
__device__ unsigned short g_ref_sorted[NCM];
__device__ double         g_accum[3];
__device__ float          g_gram[BN*CO*CO];

// ---------------- helpers ----------------
__device__ __forceinline__ unsigned int f2s(float x) {
    unsigned int u = __float_as_uint(x);
    return (u & 0x80000000u) ? ~u : (u | 0x80000000u);
}
__device__ __forceinline__ float s2f(unsigned int k) {
    unsigned int u = (k & 0x80000000u) ? (k ^ 0x80000000u) : ~k;
    return __uint_as_float(u);
}
__device__ __forceinline__ float key2f(unsigned int k16) {
    return s2f((k16 << 16) | 0x8000u);
}
__device__ __forceinline__ unsigned long long pk2(float lo, float hi) {
    unsigned long long r;
    asm("mov.b64 %0, {%1, %2};" : "=l"(r) : "f"(lo), "f"(hi));
    return r;
}
__device__ __forceinline__ void upk2(unsigned long long v, float& lo, float& hi) {
    asm("mov.b64 {%0, %1}, %2;" : "=f"(lo), "=f"(hi) : "l"(v));
}
__device__ __forceinline__ unsigned long long fma2(unsigned long long a,
                                                   unsigned long long b,
                                                   unsigned long long c) {
    unsigned long long d;
    asm("fma.rn.f32x2 %0, %1, %2, %3;" : "=l"(d) : "l"(a), "l"(b), "l"(c));
    return d;
}

__device__ __forceinline__ void block_add(double v, double* target) {
    __shared__ double sh[8];
    int tid  = threadIdx.x + threadIdx.y * blockDim.x;
    int lane = tid & 31, wid = tid >> 5;
    int nwarps = (blockDim.x * blockDim.y + 31) >> 5;
    #pragma unroll
    for (int o = 16; o > 0; o >>= 1) v += __shfl_down_sync(0xffffffffu, v, o);
    if (lane == 0) sh[wid] = v;
    __syncthreads();
    if (wid == 0) {
        v = (lane < nwarps) ? sh[lane] : 0.0;
        #pragma unroll
        for (int o = 4; o > 0; o >>= 1) v += __shfl_down_sync(0xffffffffu, v, o);
        if (lane == 0) atomicAdd(target, v);
    }
}

// ---------------- init ----------------
__global__ void init_kernel() {
    int i = blockIdx.x * 256 + threadIdx.x;
    if (i < 3) g_accum[i] = 0.0;
    if (i < BN*CO*CO) g_gram[i] = 0.0f;
}

// ------ conv + bias + relu + content-loss (fused) ------
__global__ void conv_kernel(const float* __restrict__ img, const float* __restrict__ w,
                            const float* __restrict__ b,   const float* __restrict__ ct,
                            float* __restrict__ out) {
    __shared__ float sin[3][10][34];
    __shared__ float sw[27][64];
    __shared__ float sb[64];
    const int n  = blockIdx.z;
    const int x0 = blockIdx.x * 32;
    const int y0 = blockIdx.y * 8;
    const int tid = threadIdx.y * 32 + threadIdx.x;

    for (int i = tid; i < 1728; i += 256) { int co = i / 27, tap = i % 27; sw[tap][co] = w[i]; }
    if (tid < 64) sb[tid] = b[tid];

    const float mean[3] = {0.485f, 0.456f, 0.406f};
    const float istd[3] = {1.f/0.229f, 1.f/0.224f, 1.f/0.225f};
    #pragma unroll
    for (int c = 0; c < 3; c++) {
        for (int i = tid; i < 340; i += 256) {
            int r = i / 34, cc = i % 34;
            int gy = y0 + r - 1, gx = x0 + cc - 1;
            float v = 0.f;
            if (gy >= 0 && gy < HH && gx >= 0 && gx < WW)
                v = (img[((n*3 + c)*HH + gy)*WW + gx] - mean[c]) * istd[c];
            sin[c][r][cc] = v;
        }
    }
    __syncthreads();

    const int px = threadIdx.x, py = threadIdx.y;
    float v[27];
    #pragma unroll
    for (int c = 0; c < 3; c++)
        #pragma unroll
        for (int ky = 0; ky < 3; ky++)
            #pragma unroll
            for (int kx = 0; kx < 3; kx++)
                v[c*9 + ky*3 + kx] = sin[c][py + ky][px + kx];

    const int y = y0 + py, x = x0 + px;
    float fsum = 0.f;
    #pragma unroll
    for (int cb = 0; cb < 64; cb += 16) {
        unsigned long long acc2[8];
        #pragma unroll
        for (int j = 0; j < 8; j++) acc2[j] = *(const unsigned long long*)&sb[cb + 2*j];
        #pragma unroll
        for (int t2 = 0; t2 < 27; t2++) {
            unsigned long long vv = pk2(v[t2], v[t2]);
            #pragma unroll
            for (int j = 0; j < 8; j++)
                acc2[j] = fma2(vv, *(const unsigned long long*)&sw[t2][cb + 2*j], acc2[j]);
        }
        #pragma unroll
        for (int j = 0; j < 8; j++) {
            float f0, f1;
            upk2(acc2[j], f0, f1);
            f0 = f0 > 0.f ? f0 : 0.f;
            f1 = f1 > 0.f ? f1 : 0.f;
            unsigned int ch0 = (unsigned int)(n*64 + cb + 2*j);
            unsigned int oi0 = ch0 * SS + (unsigned int)y * WW + x;
            out[oi0]      = f0;
            out[oi0 + SS] = f1;
            float d0 = f0 - ct[oi0];
            float d1 = f1 - ct[oi0 + SS];
            fsum = fmaf(d0, d0, fsum);
            fsum = fmaf(d1, d1, fsum);
        }
    }
    block_add((double)fsum, &g_accum[0]);
}

// ------ per-channel histogram of feat ------
__global__ void __launch_bounds__(1024) src_hist_kernel(const float4* __restrict__ feat) {
    extern __shared__ unsigned int sh[];
    __shared__ unsigned int zwarp[32];
    const int ch  = blockIdx.x;
    const int tid = threadIdx.x;
    const int lane = tid & 31, wid = tid >> 5;
    for (int i = tid; i < KB/2; i += 1024) sh[i] = 0;
    __syncthreads();

    const float4* p = feat + (size_t)ch * (SS/4);
    unsigned int zc = 0;
    for (int i = tid; i < SS/4; i += 1024) {
        float4 v = p[i];
        float e[4] = {v.x, v.y, v.z, v.w};
        #pragma unroll
        for (int j = 0; j < 4; j++) {
            float f = e[j];
            if (f == 0.f) { zc++; }
            else {
                unsigned int k = f2s(f) >> 16;
                atomicAdd(&sh[k >> 1], 1u << ((k & 1) * 16));
            }
        }
    }
    #pragma unroll
    for (int o = 16; o > 0; o >>= 1) zc += __shfl_down_sync(0xffffffffu, zc, o);
    if (lane == 0) zwarp[wid] = zc;
    __syncthreads();
    if (tid == 0) {
        unsigned int s = 0;
        #pragma unroll
        for (int i = 0; i < 32; i++) s += zwarp[i];
        g_zero[ch] = s;
    }

    unsigned int* g = &g_hist_src_p[(size_t)ch * (KB/2)];
    for (int i = tid; i < KB/2; i += 1024) g[i] = sh[i];
}

// ------ per-channel histogram of ref target ------
__global__ void __launch_bounds__(1024) ref_hist_kernel(const float4* __restrict__ vals) {
    extern __shared__ unsigned int sh[];
    const int ch  = blockIdx.x;
    const int tid = threadIdx.x;
    for (int i = tid; i < KB/2; i += 1024) sh[i] = 0;
    __syncthreads();

    const float4* p = vals + (size_t)ch * (MM/4);
    for (int i = tid; i < MM/4; i += 1024) {
        float4 v = p[i];
        float e[4] = {v.x, v.y, v.z, v.w};
        #pragma unroll
        for (int j = 0; j < 4; j++) {
            unsigned int k = f2s(e[j]) >> 16;
            atomicAdd(&sh[k >> 1], 1u << ((k & 1) * 16));
        }
    }
    __syncthreads();

    unsigned int* g = &g_hist_ref_p[(size_t)ch * (KB/2)];
    for (int i = tid; i < KB/2; i += 1024) g[i] = sh[i];
}

// ------ per-channel exclusive scan ------
__global__ void scan_kernel(const unsigned int* __restrict__ packed,
                            unsigned int* __restrict__ cdf,
                            const unsigned int* __restrict__ zero) {
    const int ch = blockIdx.x;
    const unsigned int* hp = packed + (size_t)ch * (KB/2);
    unsigned int* cp = cdf + (size_t)ch * KB;
    const int tid = threadIdx.x;
    const int lane = tid & 31, wid = tid >> 5;
    __shared__ unsigned int wsum[32];
    __shared__ unsigned int btot;
    unsigned int carry = 0;
    #pragma unroll
    for (int tile = 0; tile < 4; tile++) {
        const int wbase = tile * 8192 + tid * 8;
        uint4 a0 = *(const uint4*)&hp[wbase + 0];
        uint4 a1 = *(const uint4*)&hp[wbase + 4];
        unsigned int wv[8] = {a0.x,a0.y,a0.z,a0.w, a1.x,a1.y,a1.z,a1.w};
        unsigned int e[16];
        #pragma unroll
        for (int i = 0; i < 8; i++) { e[2*i] = wv[i] & 0xffffu; e[2*i+1] = wv[i] >> 16; }
        if (zero && tile == 2 && tid == 0) e[0] += zero[ch];
        unsigned int tsum = 0;
        #pragma unroll
        for (int i = 0; i < 16; i++) tsum += e[i];
        unsigned int inc = tsum;
        #pragma unroll
        for (int o = 1; o < 32; o <<= 1) {
            unsigned int nv = __shfl_up_sync(0xffffffffu, inc, o);
            if (lane >= o) inc += nv;
        }
        if (lane == 31) wsum[wid] = inc;
        __syncthreads();
        if (wid == 0) {
            unsigned int v0 = wsum[lane];
            unsigned int inc2 = v0;
            #pragma unroll
            for (int o = 1; o < 32; o <<= 1) {
                unsigned int nv = __shfl_up_sync(0xffffffffu, inc2, o);
                if (lane >= o) inc2 += nv;
            }
            wsum[lane] = inc2 - v0;
            if (lane == 31) btot = inc2;
        }
        __syncthreads();
        unsigned int run = carry + wsum[wid] + (inc - tsum);
        unsigned int o_[16];
        #pragma unroll
        for (int i = 0; i < 16; i++) { o_[i] = run; run += e[i]; }
        const int obase = tile * 16384 + tid * 16;
        *(uint4*)&cp[obase + 0]  = make_uint4(o_[0], o_[1], o_[2], o_[3]);
        *(uint4*)&cp[obase + 4]  = make_uint4(o_[4], o_[5], o_[6], o_[7]);
        *(uint4*)&cp[obase + 8]  = make_uint4(o_[8], o_[9], o_[10], o_[11]);
        *(uint4*)&cp[obase + 12] = make_uint4(o_[12], o_[13], o_[14], o_[15]);
        carry += btot;
        __syncthreads();
    }
}

// ------- counting-sort writeout: ballot-skip + uint4 fill -------
__global__ void writeout_kernel(const unsigned int* __restrict__ cdf,
                                unsigned short* __restrict__ sorted, unsigned int seglen) {
    const int ch  = blockIdx.y;
    const int lane = threadIdx.x & 31, wid = threadIdx.x >> 5;
    const int b0 = blockIdx.x * 256 + wid * 32;
    const unsigned int* __restrict__ cum = cdf + (size_t)ch * KB;
    unsigned short* __restrict__ outp = sorted + (size_t)ch * seglen;
    const int b = b0 + lane;
    unsigned int p0 = cum[b];
    unsigned int p1 = (b == KB - 1) ? seglen : cum[b + 1];
    unsigned int mask = __ballot_sync(0xffffffffu, p1 > p0);
    while (mask) {
        int k = __ffs(mask) - 1;
        mask &= mask - 1;
        unsigned int q0 = __shfl_sync(0xffffffffu, p0, k);
        unsigned int q1 = __shfl_sync(0xffffffffu, p1, k);
        unsigned short kv = (unsigned short)(b0 + k);
        unsigned int a0 = (q0 + 7u) & ~7u;
        unsigned int a1 = q1 & ~7u;
        if (a1 > a0) {
            if (q0 + lane < a0) outp[q0 + lane] = kv;
            unsigned int kk = ((unsigned int)kv << 16) | kv;
            uint4 vv = make_uint4(kk, kk, kk, kk);
            for (unsigned int p = a0 + (unsigned int)lane * 8u; p < a1; p += 256u)
                *(uint4*)&outp[p] = vv;
            if (a1 + lane < q1) outp[a1 + lane] = kv;
        } else {
            if (q0 + lane < q1) outp[q0 + lane] = kv;
        }
    }
}

// ------- hist loss: position-parallel streaming -------
__global__ void hist_loss_kernel() {
    const unsigned int t = blockIdx.x * 256u + threadIdx.x;
    const unsigned int base = t * 8u;
    const unsigned int c = base >> 18;
    const unsigned int i = base & (SS - 1);
    const float step = (float)(MM - 1) / (float)(SS - 1);
    uint4 kv = *(const uint4*)&g_src_sorted[base];
    const unsigned short* __restrict__ refq = &g_ref_sorted[(size_t)c * MM];
    unsigned int kw[4] = {kv.x, kv.y, kv.z, kv.w};
    float fsum = 0.f;
    #pragma unroll
    for (int j = 0; j < 8; j++) {
        unsigned int k16 = (kw[j >> 1] >> ((j & 1) * 16)) & 0xffffu;
        float v = key2f(k16);
        float pos = step * (float)(i + j);
        int lo = (int)pos;
        float w = pos - (float)lo;
        int hi = lo + (w > 0.f ? 1 : 0);
        if (hi > MM - 1) hi = MM - 1;
        float rlo = key2f((unsigned int)refq[lo]);
        float rhi = key2f((unsigned int)refq[hi]);
        float r = rlo * (1.0f - w) + rhi * w;
        float d = v - r;
        fsum = fmaf(d, d, fsum);
    }
    block_add((double)fsum, &g_accum[2]);
}

// ====== gram via classic mma.sync (HMMA, bf16): C[64,64] = F_n · F_nᵀ ======
// Per block: one batch n, one K-chunk of 4096. 8 warps, each owns m16 x n32.
// A and B fragments come from the SAME smem tile (symmetric product), loaded
// with plain LDS.b32 — the m16n8k16 A-frag and B-frag per-lane maps coincide:
// reg word = tile_word[row * 68 + kword + t4], rows differ (m vs n).
#define GCHUNK 4096
#define GKT    128
__global__ void __launch_bounds__(256) gram_mma_kernel(const float* __restrict__ feat) {
    __shared__ __align__(16) unsigned short tile[64 * 136];  // pitch 136 bf16 = 68 words
    const int nb  = blockIdx.y;          // batch
    const int kc  = blockIdx.x;          // K chunk
    const int tid = threadIdx.x;
    const int w   = tid >> 5, lane = tid & 31;
    const int g   = lane >> 2, t4 = lane & 3;   // groupID, threadID-in-group
    const int m0  = (w & 3) * 16;
    const int n0  = (w >> 2) * 32;
    float c[4][4] = {};
    const size_t fbase = (size_t)(nb * 64) * SS + (size_t)kc * GCHUNK;

    for (int kt = 0; kt < GCHUNK; kt += GKT) {
        __syncthreads();
        // load 64 rows x 128 f32 -> bf16 smem tile
        #pragma unroll
        for (int j = 0; j < 8; j++) {
            int e4  = j * 256 + tid;          // 2048 float4 = 64 rows x 32
            int row = e4 >> 5, c4 = e4 & 31;
            float4 f = *(const float4*)&feat[fbase + (size_t)row * SS + kt + c4 * 4];
            __nv_bfloat162 p0 = __float22bfloat162_rn(make_float2(f.x, f.y));
            __nv_bfloat162 p1 = __float22bfloat162_rn(make_float2(f.z, f.w));
            unsigned long long pv = ((unsigned long long)(*(unsigned int*)&p1) << 32) |
                                     (*(unsigned int*)&p0);
            *(unsigned long long*)&tile[row * 136 + c4 * 4] = pv;
        }
        __syncthreads();
        const unsigned int* tw = (const unsigned int*)tile;   // word view, pitch 68
        #pragma unroll
        for (int kk = 0; kk < GKT; kk += 16) {
            int kw = (kk >> 1) + t4;
            unsigned int a0 = tw[(m0 + g)     * 68 + kw];
            unsigned int a1 = tw[(m0 + g + 8) * 68 + kw];
            unsigned int a2 = tw[(m0 + g)     * 68 + kw + 4];
            unsigned int a3 = tw[(m0 + g + 8) * 68 + kw + 4];
            #pragma unroll
            for (int nt = 0; nt < 4; nt++) {
                int nr = n0 + nt * 8 + g;
                unsigned int b0 = tw[nr * 68 + kw];
                unsigned int b1 = tw[nr * 68 + kw + 4];
                asm volatile(
                    "mma.sync.aligned.m16n8k16.row.col.f32.bf16.bf16.f32 "
                    "{%0,%1,%2,%3}, {%4,%5,%6,%7}, {%8,%9}, {%0,%1,%2,%3};"
                    : "+f"(c[nt][0]), "+f"(c[nt][1]), "+f"(c[nt][2]), "+f"(c[nt][3])
                    : "r"(a0), "r"(a1), "r"(a2), "r"(a3), "r"(b0), "r"(b1));
            }
        }
    }
    float* gg = &g_gram[nb * 4096];
    #pragma unroll
    for (int nt = 0; nt < 4; nt++) {
        int col = n0 + nt * 8 + t4 * 2;
        atomicAdd(&gg[(m0 + g)     * 64 + col],     c[nt][0]);
        atomicAdd(&gg[(m0 + g)     * 64 + col + 1], c[nt][1]);
        atomicAdd(&gg[(m0 + g + 8) * 64 + col],     c[nt][2]);
        atomicAdd(&gg[(m0 + g + 8) * 64 + col + 1], c[nt][3]);
    }
}

// ---------------- style loss ----------------
__global__ void style_kernel(const float* __restrict__ tgt) {
    int i = blockIdx.x * 256 + threadIdx.x;
    double d = 0.0;
    if (i < BN*CO*CO) {
        float g = g_gram[i] * (1.0f / ((float)CO * HH * WW));
        float df = g - tgt[i];
        d = (double)df * (double)df;
    }
    block_add(d, &g_accum[1]);
}

// ---------------- finalize ----------------
__global__ void finalize_kernel(float* __restrict__ out) {
    if (threadIdx.x == 0) {
        out[NCS + 0] = (float)(g_accum[0] / (double)NCS);
        out[NCS + 1] = (float)(g_accum[1] / (double)(BN*CO*CO));
        out[NCS + 2] = (float)(g_accum[2] / (double)NCS);
    }
}

// ---------------- launch: fork/join streams ----------------
extern "C" void kernel_launch(void* const* d_in, const int* in_sizes, int n_in,
                              void* d_out, int out_size) {
    const float* img  = (const float*)d_in[0];
    const float* w    = (const float*)d_in[1];
    const float* b    = (const float*)d_in[2];
    const float* ct   = (const float*)d_in[3];
    const float* stg  = (const float*)d_in[4];
    const float* hist = (const float*)d_in[5];
    float* out = (float*)d_out;

    void *p_hsp, *p_hrp, *p_cs, *p_cr, *p_z, *p_ss, *p_rs;
    cudaGetSymbolAddress(&p_hsp, g_hist_src_p);
    cudaGetSymbolAddress(&p_hrp, g_hist_ref_p);
    cudaGetSymbolAddress(&p_cs,  g_cdf_src);
    cudaGetSymbolAddress(&p_cr,  g_cdf_ref);
    cudaGetSymbolAddress(&p_z,   g_zero);
    cudaGetSymbolAddress(&p_ss,  g_src_sorted);
    cudaGetSymbolAddress(&p_rs,  g_ref_sorted);

    static cudaStream_t sB = 0, sC = 0;
    static cudaEvent_t eInit = 0, eConv = 0, eRef = 0, eC = 0;
    if (!sB) {
        cudaStreamCreateWithFlags(&sB, cudaStreamNonBlocking);
        cudaStreamCreateWithFlags(&sC, cudaStreamNonBlocking);
        cudaEventCreateWithFlags(&eInit, cudaEventDisableTiming);
        cudaEventCreateWithFlags(&eConv, cudaEventDisableTiming);
        cudaEventCreateWithFlags(&eRef,  cudaEventDisableTiming);
        cudaEventCreateWithFlags(&eC,    cudaEventDisableTiming);
        cudaFuncSetAttribute(src_hist_kernel, cudaFuncAttributeMaxDynamicSharedMemorySize, 131072);
        cudaFuncSetAttribute(ref_hist_kernel, cudaFuncAttributeMaxDynamicSharedMemorySize, 131072);
    }

    init_kernel<<<64, 256>>>();
    cudaEventRecord(eInit, 0);

    // chain B: ref-target pipeline
    cudaStreamWaitEvent(sB, eInit, 0);
    ref_hist_kernel<<<NC, 1024, 131072, sB>>>((const float4*)hist);
    scan_kernel<<<NC, 1024, 0, sB>>>((const unsigned int*)p_hrp, (unsigned int*)p_cr,
                                     (const unsigned int*)0);
    writeout_kernel<<<dim3(KB/256, NC), 256, 0, sB>>>((const unsigned int*)p_cr,
                                                      (unsigned short*)p_rs, (unsigned int)MM);
    cudaEventRecord(eRef, sB);

    // stream 0: conv
    dim3 cgrid(WW/32, HH/8, BN), cblk(32, 8);
    conv_kernel<<<cgrid, cblk>>>(img, w, b, ct, out);
    cudaEventRecord(eConv, 0);

    // chain C: tensor-core (HMMA) gram + style
    cudaStreamWaitEvent(sC, eConv, 0);
    gram_mma_kernel<<<dim3(SS/GCHUNK, BN), 256, 0, sC>>>(out);
    style_kernel<<<(BN*CO*CO + 255)/256, 256, 0, sC>>>(stg);
    cudaEventRecord(eC, sC);

    // stream 0: src histogram pipeline
    src_hist_kernel<<<NC, 1024, 131072>>>((const float4*)out);
    scan_kernel<<<NC, 1024>>>((const unsigned int*)p_hsp, (unsigned int*)p_cs,
                              (const unsigned int*)p_z);
    writeout_kernel<<<dim3(KB/256, NC), 256>>>((const unsigned int*)p_cs,
                                               (unsigned short*)p_ss, (unsigned int)SS);

    cudaStreamWaitEvent(0, eRef, 0);
    hist_loss_kernel<<<NCS/2048, 256>>>();

    cudaStreamWaitEvent(0, eC, 0);
    finalize_kernel<<<1, 32>>>(out);

    (void)in_sizes; (void)n_in; (void)out_size;
}

// round 17
// speedup vs baseline: 2.6987x; 1.1690x over previous
#include <cuda_runtime.h>
#include <cuda_bf16.h>

#define BN   4
#define CIN  3
#define CO   64
#define HH   512
#define WW   512
#define SS   (HH*WW)        /* 262144 = 2^18 */
#define NC   (BN*CO)        /* 256 */
#define HR   448
#define MM   (HR*HR)        /* 200704 */
#define NCS  (NC*SS)        /* 67108864 */
#define NCM  (NC*MM)        /* 51380224 */
#define KB   32768          /* bins per channel (15-bit sortable key) */

// ---------------- static device scratch (no runtime allocation) ----------------
__device__ unsigned int   g_hist_src_p[NC*KB/2];  // packed u16 counts (16 MB)
__device__ unsigned int   g_hist_ref_p[NC*KB/2];  // packed u16 counts (16 MB)
__device__ unsigned int   g_cdf_src[NC*KB];       // u32 exclusive CDF (32 MB)
__device__ unsigned int   g_cdf_ref[NC*KB];       // u32 exclusive CDF (32 MB)
__device__ unsigned int   g_zero[NC];
__device__ unsigned short g_src_sorted[NCS];
__device__ unsigned short g_ref_sorted[NCM];
__device__ double         g_accum[3];
__device__ float          g_gram[BN*CO*CO];

// ---------------- helpers ----------------
__device__ __forceinline__ unsigned int f2s(float x) {
    unsigned int u = __float_as_uint(x);
    return (u & 0x80000000u) ? ~u : (u | 0x80000000u);
}
__device__ __forceinline__ float s2f(unsigned int k) {
    unsigned int u = (k & 0x80000000u) ? (k ^ 0x80000000u) : ~k;
    return __uint_as_float(u);
}
// 15-bit key -> float (midpoint of 17-bit truncation bucket)
__device__ __forceinline__ float key2f(unsigned int k15) {
    return s2f((k15 << 17) | 0x10000u);
}
__device__ __forceinline__ unsigned long long pk2(float lo, float hi) {
    unsigned long long r;
    asm("mov.b64 %0, {%1, %2};" : "=l"(r) : "f"(lo), "f"(hi));
    return r;
}
__device__ __forceinline__ void upk2(unsigned long long v, float& lo, float& hi) {
    asm("mov.b64 {%0, %1}, %2;" : "=f"(lo), "=f"(hi) : "l"(v));
}
__device__ __forceinline__ unsigned long long fma2(unsigned long long a,
                                                   unsigned long long b,
                                                   unsigned long long c) {
    unsigned long long d;
    asm("fma.rn.f32x2 %0, %1, %2, %3;" : "=l"(d) : "l"(a), "l"(b), "l"(c));
    return d;
}

__device__ __forceinline__ void block_add(double v, double* target) {
    __shared__ double sh[8];
    int tid  = threadIdx.x + threadIdx.y * blockDim.x;
    int lane = tid & 31, wid = tid >> 5;
    int nwarps = (blockDim.x * blockDim.y + 31) >> 5;
    #pragma unroll
    for (int o = 16; o > 0; o >>= 1) v += __shfl_down_sync(0xffffffffu, v, o);
    if (lane == 0) sh[wid] = v;
    __syncthreads();
    if (wid == 0) {
        v = (lane < nwarps) ? sh[lane] : 0.0;
        #pragma unroll
        for (int o = 4; o > 0; o >>= 1) v += __shfl_down_sync(0xffffffffu, v, o);
        if (lane == 0) atomicAdd(target, v);
    }
}

// ---------------- init ----------------
__global__ void init_kernel() {
    int i = blockIdx.x * 256 + threadIdx.x;
    if (i < 3) g_accum[i] = 0.0;
    if (i < BN*CO*CO) g_gram[i] = 0.0f;
}

// ------ conv + bias + relu + content-loss (fused) ------
__global__ void conv_kernel(const float* __restrict__ img, const float* __restrict__ w,
                            const float* __restrict__ b,   const float* __restrict__ ct,
                            float* __restrict__ out) {
    __shared__ float sin[3][10][34];
    __shared__ float sw[27][64];
    __shared__ float sb[64];
    const int n  = blockIdx.z;
    const int x0 = blockIdx.x * 32;
    const int y0 = blockIdx.y * 8;
    const int tid = threadIdx.y * 32 + threadIdx.x;

    for (int i = tid; i < 1728; i += 256) { int co = i / 27, tap = i % 27; sw[tap][co] = w[i]; }
    if (tid < 64) sb[tid] = b[tid];

    const float mean[3] = {0.485f, 0.456f, 0.406f};
    const float istd[3] = {1.f/0.229f, 1.f/0.224f, 1.f/0.225f};
    #pragma unroll
    for (int c = 0; c < 3; c++) {
        for (int i = tid; i < 340; i += 256) {
            int r = i / 34, cc = i % 34;
            int gy = y0 + r - 1, gx = x0 + cc - 1;
            float v = 0.f;
            if (gy >= 0 && gy < HH && gx >= 0 && gx < WW)
                v = (img[((n*3 + c)*HH + gy)*WW + gx] - mean[c]) * istd[c];
            sin[c][r][cc] = v;
        }
    }
    __syncthreads();

    const int px = threadIdx.x, py = threadIdx.y;
    float v[27];
    #pragma unroll
    for (int c = 0; c < 3; c++)
        #pragma unroll
        for (int ky = 0; ky < 3; ky++)
            #pragma unroll
            for (int kx = 0; kx < 3; kx++)
                v[c*9 + ky*3 + kx] = sin[c][py + ky][px + kx];

    const int y = y0 + py, x = x0 + px;
    float fsum = 0.f;
    #pragma unroll
    for (int cb = 0; cb < 64; cb += 16) {
        unsigned long long acc2[8];
        #pragma unroll
        for (int j = 0; j < 8; j++) acc2[j] = *(const unsigned long long*)&sb[cb + 2*j];
        #pragma unroll
        for (int t2 = 0; t2 < 27; t2++) {
            unsigned long long vv = pk2(v[t2], v[t2]);
            #pragma unroll
            for (int j = 0; j < 8; j++)
                acc2[j] = fma2(vv, *(const unsigned long long*)&sw[t2][cb + 2*j], acc2[j]);
        }
        #pragma unroll
        for (int j = 0; j < 8; j++) {
            float f0, f1;
            upk2(acc2[j], f0, f1);
            f0 = f0 > 0.f ? f0 : 0.f;
            f1 = f1 > 0.f ? f1 : 0.f;
            unsigned int ch0 = (unsigned int)(n*64 + cb + 2*j);
            unsigned int oi0 = ch0 * SS + (unsigned int)y * WW + x;
            out[oi0]      = f0;
            out[oi0 + SS] = f1;
            float d0 = f0 - ct[oi0];
            float d1 = f1 - ct[oi0 + SS];
            fsum = fmaf(d0, d0, fsum);
            fsum = fmaf(d1, d1, fsum);
        }
    }
    block_add((double)fsum, &g_accum[0]);
}

// ------ per-channel histogram of feat (15-bit keys, 64 KB smem -> 2 blocks/SM) ------
__global__ void __launch_bounds__(1024) src_hist_kernel(const float4* __restrict__ feat) {
    extern __shared__ unsigned int sh[];   // KB/2 = 16384 words
    __shared__ unsigned int zwarp[32];
    const int ch  = blockIdx.x;
    const int tid = threadIdx.x;
    const int lane = tid & 31, wid = tid >> 5;
    for (int i = tid; i < KB/2; i += 1024) sh[i] = 0;
    __syncthreads();

    const float4* p = feat + (size_t)ch * (SS/4);
    unsigned int zc = 0;
    for (int i = tid; i < SS/4; i += 1024) {
        float4 v = p[i];
        float e[4] = {v.x, v.y, v.z, v.w};
        #pragma unroll
        for (int j = 0; j < 4; j++) {
            float f = e[j];
            if (f == 0.f) { zc++; }
            else {
                unsigned int k = f2s(f) >> 17;
                atomicAdd(&sh[k >> 1], 1u << ((k & 1) * 16));
            }
        }
    }
    #pragma unroll
    for (int o = 16; o > 0; o >>= 1) zc += __shfl_down_sync(0xffffffffu, zc, o);
    if (lane == 0) zwarp[wid] = zc;
    __syncthreads();
    if (tid == 0) {
        unsigned int s = 0;
        #pragma unroll
        for (int i = 0; i < 32; i++) s += zwarp[i];
        g_zero[ch] = s;
    }

    unsigned int* g = &g_hist_src_p[(size_t)ch * (KB/2)];
    for (int i = tid; i < KB/2; i += 1024) g[i] = sh[i];
}

// ------ per-channel histogram of ref target ------
__global__ void __launch_bounds__(1024) ref_hist_kernel(const float4* __restrict__ vals) {
    extern __shared__ unsigned int sh[];
    const int ch  = blockIdx.x;
    const int tid = threadIdx.x;
    for (int i = tid; i < KB/2; i += 1024) sh[i] = 0;
    __syncthreads();

    const float4* p = vals + (size_t)ch * (MM/4);
    for (int i = tid; i < MM/4; i += 1024) {
        float4 v = p[i];
        float e[4] = {v.x, v.y, v.z, v.w};
        #pragma unroll
        for (int j = 0; j < 4; j++) {
            unsigned int k = f2s(e[j]) >> 17;
            atomicAdd(&sh[k >> 1], 1u << ((k & 1) * 16));
        }
    }
    __syncthreads();

    unsigned int* g = &g_hist_ref_p[(size_t)ch * (KB/2)];
    for (int i = tid; i < KB/2; i += 1024) g[i] = sh[i];
}

// ------ per-channel exclusive scan: packed u16 hist -> u32 CDF (2 tiles) ------
__global__ void scan_kernel(const unsigned int* __restrict__ packed,
                            unsigned int* __restrict__ cdf,
                            const unsigned int* __restrict__ zero) {
    const int ch = blockIdx.x;
    const unsigned int* hp = packed + (size_t)ch * (KB/2);
    unsigned int* cp = cdf + (size_t)ch * KB;
    const int tid = threadIdx.x;
    const int lane = tid & 31, wid = tid >> 5;
    __shared__ unsigned int wsum[32];
    __shared__ unsigned int btot;
    unsigned int carry = 0;
    #pragma unroll
    for (int tile = 0; tile < 2; tile++) {
        const int wbase = tile * 8192 + tid * 8;
        uint4 a0 = *(const uint4*)&hp[wbase + 0];
        uint4 a1 = *(const uint4*)&hp[wbase + 4];
        unsigned int wv[8] = {a0.x,a0.y,a0.z,a0.w, a1.x,a1.y,a1.z,a1.w};
        unsigned int e[16];
        #pragma unroll
        for (int i = 0; i < 8; i++) { e[2*i] = wv[i] & 0xffffu; e[2*i+1] = wv[i] >> 16; }
        if (zero && tile == 1 && tid == 0) e[0] += zero[ch];  // bin 0x4000 = 16384
        unsigned int tsum = 0;
        #pragma unroll
        for (int i = 0; i < 16; i++) tsum += e[i];
        unsigned int inc = tsum;
        #pragma unroll
        for (int o = 1; o < 32; o <<= 1) {
            unsigned int nv = __shfl_up_sync(0xffffffffu, inc, o);
            if (lane >= o) inc += nv;
        }
        if (lane == 31) wsum[wid] = inc;
        __syncthreads();
        if (wid == 0) {
            unsigned int v0 = wsum[lane];
            unsigned int inc2 = v0;
            #pragma unroll
            for (int o = 1; o < 32; o <<= 1) {
                unsigned int nv = __shfl_up_sync(0xffffffffu, inc2, o);
                if (lane >= o) inc2 += nv;
            }
            wsum[lane] = inc2 - v0;
            if (lane == 31) btot = inc2;
        }
        __syncthreads();
        unsigned int run = carry + wsum[wid] + (inc - tsum);
        unsigned int o_[16];
        #pragma unroll
        for (int i = 0; i < 16; i++) { o_[i] = run; run += e[i]; }
        const int obase = tile * 16384 + tid * 16;
        *(uint4*)&cp[obase + 0]  = make_uint4(o_[0], o_[1], o_[2], o_[3]);
        *(uint4*)&cp[obase + 4]  = make_uint4(o_[4], o_[5], o_[6], o_[7]);
        *(uint4*)&cp[obase + 8]  = make_uint4(o_[8], o_[9], o_[10], o_[11]);
        *(uint4*)&cp[obase + 12] = make_uint4(o_[12], o_[13], o_[14], o_[15]);
        carry += btot;
        __syncthreads();
    }
}

// ------- counting-sort writeout: ballot-skip + uint4 fill -------
__global__ void writeout_kernel(const unsigned int* __restrict__ cdf,
                                unsigned short* __restrict__ sorted, unsigned int seglen) {
    const int ch  = blockIdx.y;
    const int lane = threadIdx.x & 31, wid = threadIdx.x >> 5;
    const int b0 = blockIdx.x * 256 + wid * 32;
    const unsigned int* __restrict__ cum = cdf + (size_t)ch * KB;
    unsigned short* __restrict__ outp = sorted + (size_t)ch * seglen;
    const int b = b0 + lane;
    unsigned int p0 = cum[b];
    unsigned int p1 = (b == KB - 1) ? seglen : cum[b + 1];
    unsigned int mask = __ballot_sync(0xffffffffu, p1 > p0);
    while (mask) {
        int k = __ffs(mask) - 1;
        mask &= mask - 1;
        unsigned int q0 = __shfl_sync(0xffffffffu, p0, k);
        unsigned int q1 = __shfl_sync(0xffffffffu, p1, k);
        unsigned short kv = (unsigned short)(b0 + k);
        unsigned int a0 = (q0 + 7u) & ~7u;
        unsigned int a1 = q1 & ~7u;
        if (a1 > a0) {
            if (q0 + lane < a0) outp[q0 + lane] = kv;
            unsigned int kk = ((unsigned int)kv << 16) | kv;
            uint4 vv = make_uint4(kk, kk, kk, kk);
            for (unsigned int p = a0 + (unsigned int)lane * 8u; p < a1; p += 256u)
                *(uint4*)&outp[p] = vv;
            if (a1 + lane < q1) outp[a1 + lane] = kv;
        } else {
            if (q0 + lane < q1) outp[q0 + lane] = kv;
        }
    }
}

// ------- hist loss: position-parallel streaming -------
__global__ void hist_loss_kernel() {
    const unsigned int t = blockIdx.x * 256u + threadIdx.x;
    const unsigned int base = t * 8u;
    const unsigned int c = base >> 18;
    const unsigned int i = base & (SS - 1);
    const float step = (float)(MM - 1) / (float)(SS - 1);
    uint4 kv = *(const uint4*)&g_src_sorted[base];
    const unsigned short* __restrict__ refq = &g_ref_sorted[(size_t)c * MM];
    unsigned int kw[4] = {kv.x, kv.y, kv.z, kv.w};
    float fsum = 0.f;
    #pragma unroll
    for (int j = 0; j < 8; j++) {
        unsigned int k15 = (kw[j >> 1] >> ((j & 1) * 16)) & 0xffffu;
        float v = key2f(k15);
        float pos = step * (float)(i + j);
        int lo = (int)pos;
        float w = pos - (float)lo;
        int hi = lo + (w > 0.f ? 1 : 0);
        if (hi > MM - 1) hi = MM - 1;
        float rlo = key2f((unsigned int)refq[lo]);
        float rhi = key2f((unsigned int)refq[hi]);
        float r = rlo * (1.0f - w) + rhi * w;
        float d = v - r;
        fsum = fmaf(d, d, fsum);
    }
    block_add((double)fsum, &g_accum[2]);
}

// ====== gram via classic mma.sync (HMMA, bf16): C[64,64] = F_n · F_nᵀ ======
#define GCHUNK 4096
#define GKT    128
__global__ void __launch_bounds__(256) gram_mma_kernel(const float* __restrict__ feat) {
    __shared__ __align__(16) unsigned short tile[64 * 136];
    const int nb  = blockIdx.y;
    const int kc  = blockIdx.x;
    const int tid = threadIdx.x;
    const int w   = tid >> 5, lane = tid & 31;
    const int g   = lane >> 2, t4 = lane & 3;
    const int m0  = (w & 3) * 16;
    const int n0  = (w >> 2) * 32;
    float c[4][4] = {};
    const size_t fbase = (size_t)(nb * 64) * SS + (size_t)kc * GCHUNK;

    for (int kt = 0; kt < GCHUNK; kt += GKT) {
        __syncthreads();
        #pragma unroll
        for (int j = 0; j < 8; j++) {
            int e4  = j * 256 + tid;
            int row = e4 >> 5, c4 = e4 & 31;
            float4 f = *(const float4*)&feat[fbase + (size_t)row * SS + kt + c4 * 4];
            __nv_bfloat162 p0 = __float22bfloat162_rn(make_float2(f.x, f.y));
            __nv_bfloat162 p1 = __float22bfloat162_rn(make_float2(f.z, f.w));
            unsigned long long pv = ((unsigned long long)(*(unsigned int*)&p1) << 32) |
                                     (*(unsigned int*)&p0);
            *(unsigned long long*)&tile[row * 136 + c4 * 4] = pv;
        }
        __syncthreads();
        const unsigned int* tw = (const unsigned int*)tile;
        #pragma unroll
        for (int kk = 0; kk < GKT; kk += 16) {
            int kw = (kk >> 1) + t4;
            unsigned int a0 = tw[(m0 + g)     * 68 + kw];
            unsigned int a1 = tw[(m0 + g + 8) * 68 + kw];
            unsigned int a2 = tw[(m0 + g)     * 68 + kw + 4];
            unsigned int a3 = tw[(m0 + g + 8) * 68 + kw + 4];
            #pragma unroll
            for (int nt = 0; nt < 4; nt++) {
                int nr = n0 + nt * 8 + g;
                unsigned int b0 = tw[nr * 68 + kw];
                unsigned int b1 = tw[nr * 68 + kw + 4];
                asm volatile(
                    "mma.sync.aligned.m16n8k16.row.col.f32.bf16.bf16.f32 "
                    "{%0,%1,%2,%3}, {%4,%5,%6,%7}, {%8,%9}, {%0,%1,%2,%3};"
                    : "+f"(c[nt][0]), "+f"(c[nt][1]), "+f"(c[nt][2]), "+f"(c[nt][3])
                    : "r"(a0), "r"(a1), "r"(a2), "r"(a3), "r"(b0), "r"(b1));
            }
        }
    }
    float* gg = &g_gram[nb * 4096];
    #pragma unroll
    for (int nt = 0; nt < 4; nt++) {
        int col = n0 + nt * 8 + t4 * 2;
        atomicAdd(&gg[(m0 + g)     * 64 + col],     c[nt][0]);
        atomicAdd(&gg[(m0 + g)     * 64 + col + 1], c[nt][1]);
        atomicAdd(&gg[(m0 + g + 8) * 64 + col],     c[nt][2]);
        atomicAdd(&gg[(m0 + g + 8) * 64 + col + 1], c[nt][3]);
    }
}

// ---------------- style loss ----------------
__global__ void style_kernel(const float* __restrict__ tgt) {
    int i = blockIdx.x * 256 + threadIdx.x;
    double d = 0.0;
    if (i < BN*CO*CO) {
        float g = g_gram[i] * (1.0f / ((float)CO * HH * WW));
        float df = g - tgt[i];
        d = (double)df * (double)df;
    }
    block_add(d, &g_accum[1]);
}

// ---------------- finalize ----------------
__global__ void finalize_kernel(float* __restrict__ out) {
    if (threadIdx.x == 0) {
        out[NCS + 0] = (float)(g_accum[0] / (double)NCS);
        out[NCS + 1] = (float)(g_accum[1] / (double)(BN*CO*CO));
        out[NCS + 2] = (float)(g_accum[2] / (double)NCS);
    }
}

// ---------------- launch: fork/join streams ----------------
extern "C" void kernel_launch(void* const* d_in, const int* in_sizes, int n_in,
                              void* d_out, int out_size) {
    const float* img  = (const float*)d_in[0];
    const float* w    = (const float*)d_in[1];
    const float* b    = (const float*)d_in[2];
    const float* ct   = (const float*)d_in[3];
    const float* stg  = (const float*)d_in[4];
    const float* hist = (const float*)d_in[5];
    float* out = (float*)d_out;

    void *p_hsp, *p_hrp, *p_cs, *p_cr, *p_z, *p_ss, *p_rs;
    cudaGetSymbolAddress(&p_hsp, g_hist_src_p);
    cudaGetSymbolAddress(&p_hrp, g_hist_ref_p);
    cudaGetSymbolAddress(&p_cs,  g_cdf_src);
    cudaGetSymbolAddress(&p_cr,  g_cdf_ref);
    cudaGetSymbolAddress(&p_z,   g_zero);
    cudaGetSymbolAddress(&p_ss,  g_src_sorted);
    cudaGetSymbolAddress(&p_rs,  g_ref_sorted);

    static cudaStream_t sB = 0, sC = 0;
    static cudaEvent_t eInit = 0, eConv = 0, eRef = 0, eC = 0;
    if (!sB) {
        cudaStreamCreateWithFlags(&sB, cudaStreamNonBlocking);
        cudaStreamCreateWithFlags(&sC, cudaStreamNonBlocking);
        cudaEventCreateWithFlags(&eInit, cudaEventDisableTiming);
        cudaEventCreateWithFlags(&eConv, cudaEventDisableTiming);
        cudaEventCreateWithFlags(&eRef,  cudaEventDisableTiming);
        cudaEventCreateWithFlags(&eC,    cudaEventDisableTiming);
        cudaFuncSetAttribute(src_hist_kernel, cudaFuncAttributeMaxDynamicSharedMemorySize, 65536);
        cudaFuncSetAttribute(ref_hist_kernel, cudaFuncAttributeMaxDynamicSharedMemorySize, 65536);
    }

    init_kernel<<<64, 256>>>();
    cudaEventRecord(eInit, 0);

    // chain B: ref-target pipeline
    cudaStreamWaitEvent(sB, eInit, 0);
    ref_hist_kernel<<<NC, 1024, 65536, sB>>>((const float4*)hist);
    scan_kernel<<<NC, 1024, 0, sB>>>((const unsigned int*)p_hrp, (unsigned int*)p_cr,
                                     (const unsigned int*)0);
    writeout_kernel<<<dim3(KB/256, NC), 256, 0, sB>>>((const unsigned int*)p_cr,
                                                      (unsigned short*)p_rs, (unsigned int)MM);
    cudaEventRecord(eRef, sB);

    // stream 0: conv
    dim3 cgrid(WW/32, HH/8, BN), cblk(32, 8);
    conv_kernel<<<cgrid, cblk>>>(img, w, b, ct, out);
    cudaEventRecord(eConv, 0);

    // chain C: tensor-core (HMMA) gram + style
    cudaStreamWaitEvent(sC, eConv, 0);
    gram_mma_kernel<<<dim3(SS/GCHUNK, BN), 256, 0, sC>>>(out);
    style_kernel<<<(BN*CO*CO + 255)/256, 256, 0, sC>>>(stg);
    cudaEventRecord(eC, sC);

    // stream 0: src histogram pipeline
    src_hist_kernel<<<NC, 1024, 65536>>>((const float4*)out);
    scan_kernel<<<NC, 1024>>>((const unsigned int*)p_hsp, (unsigned int*)p_cs,
                              (const unsigned int*)p_z);
    writeout_kernel<<<dim3(KB/256, NC), 256>>>((const unsigned int*)p_cs,
                                               (unsigned short*)p_ss, (unsigned int)SS);

    cudaStreamWaitEvent(0, eRef, 0);
    hist_loss_kernel<<<NCS/2048, 256>>>();

    cudaStreamWaitEvent(0, eC, 0);
    finalize_kernel<<<1, 32>>>(out);

    (void)in_sizes; (void)n_in; (void)out_size;
}